// round 7
// baseline (speedup 1.0000x reference)
#include <cuda_runtime.h>
#include <cuda_bf16.h>
#include <cstdint>

#define BB  8
#define CC  256
#define PP  64
#define HWS 4096

// ---------------- scratch (device globals) ----------------------------------
__device__ __align__(128) __nv_bfloat16 g_topH[BB * HWS * PP];  // [B][HW][P] hi
__device__ __align__(128) __nv_bfloat16 g_topL[BB * HWS * PP];  // lo
__device__ __align__(128) __nv_bfloat16 g_cenH[BB * HWS * PP];
__device__ __align__(128) __nv_bfloat16 g_cenL[BB * HWS * PP];
__device__ __align__(128) float g_bottomT[BB * CC * HWS];       // [B][C][HW]
__device__ __align__(128) float g_S[134217728];                 // [B][HW][HW]; holds E
__device__ __align__(128) float g_attn[BB * HWS * CC];          // [B][HW][C]
__device__ float g_partialS[BB * 1024];
__device__ float g_sum[BB];

// ---------------- helpers ----------------------------------------------------
__device__ __forceinline__ float tf32r(float x) {
    uint32_t u;
    asm("cvt.rna.tf32.f32 %0, %1;" : "=r"(u) : "f"(x));
    return __uint_as_float(u);
}

__device__ __forceinline__ void mma8(float* d, const uint32_t* a, const uint32_t* b) {
    asm volatile(
        "mma.sync.aligned.m16n8k8.row.col.f32.tf32.tf32.f32 "
        "{%0,%1,%2,%3}, {%4,%5,%6,%7}, {%8,%9}, {%0,%1,%2,%3};"
        : "+f"(d[0]), "+f"(d[1]), "+f"(d[2]), "+f"(d[3])
        : "r"(a[0]), "r"(a[1]), "r"(a[2]), "r"(a[3]), "r"(b[0]), "r"(b[1]));
}

__device__ __forceinline__ void mma16bf(float* d, const uint32_t* a, const uint32_t* b) {
    asm volatile(
        "mma.sync.aligned.m16n8k16.row.col.f32.bf16.bf16.f32 "
        "{%0,%1,%2,%3}, {%4,%5,%6,%7}, {%8,%9}, {%0,%1,%2,%3};"
        : "+f"(d[0]), "+f"(d[1]), "+f"(d[2]), "+f"(d[3])
        : "r"(a[0]), "r"(a[1]), "r"(a[2]), "r"(a[3]), "r"(b[0]), "r"(b[1]));
}

// swizzled index in a [128 rows][32 u32] panel
__device__ __forceinline__ int swidx(int r, int k) {
    return r * 32 + (((k >> 2) ^ (r & 7)) << 2) + (k & 3);
}

// ---------------- register-staged panel fetch/commit -------------------------
struct RT { float4 v[4]; };

__device__ __forceinline__ RT fetchK(const float* src, int lda, int k0) {
    RT rt;
    int r  = threadIdx.x >> 1;
    int kq = (threadIdx.x & 1) * 4;
    const float4* row = (const float4*)(src + (size_t)r * lda + k0) + kq;
#pragma unroll
    for (int j = 0; j < 4; j++) rt.v[j] = row[j];
    return rt;
}

template<bool ADDZ>
__device__ __forceinline__ RT fetchIm2col(const float* xb, const float* zb, int n0, int k0) {
    RT rt;
    int r  = threadIdx.x >> 1;
    int kq = (threadIdx.x & 1) * 4;
    int n  = n0 + r;
    int h  = n >> 6, w = n & 63;
#pragma unroll
    for (int j = 0; j < 4; j++) {
        float vv[4];
#pragma unroll
        for (int e = 0; e < 4; e++) {
            int k  = k0 + (kq + j) * 4 + e;
            int ci = k / 9;
            int rr = k - ci * 9;
            int dh = rr / 3 - 1;
            int dw = rr - (rr / 3) * 3 - 1;
            int hh = h + dh, ww = w + dw;
            float v = 0.f;
            if ((unsigned)hh < 64u && (unsigned)ww < 64u) {
                int off = ci * HWS + hh * 64 + ww;
                v = xb[off];
                if (ADDZ) v += zb[off];
            }
            vv[e] = v;
        }
        rt.v[j] = make_float4(vv[0], vv[1], vv[2], vv[3]);
    }
    return rt;
}

__device__ __forceinline__ void commitP(float* pan, const RT& rt) {
    int r  = threadIdx.x >> 1;
    int kq = (threadIdx.x & 1) * 4;
#pragma unroll
    for (int j = 0; j < 4; j++) {
        float4 v = rt.v[j];
        v.x = tf32r(v.x); v.y = tf32r(v.y); v.z = tf32r(v.z); v.w = tf32r(v.w);
        *(float4*)&pan[r * 32 + (((kq + j) ^ (r & 7)) << 2)] = v;
    }
}

// ---------------- warp compute over one k32 tf32 panel -----------------------
__device__ __forceinline__ void panel_mma(float acc[4][4][4],
                                          const float* As, const float* Bs,
                                          int warp_m, int warp_n, int lane) {
    const uint32_t* Au = (const uint32_t*)As;
    const uint32_t* Bu = (const uint32_t*)Bs;
    int g = lane >> 2, t = lane & 3;
#pragma unroll
    for (int ks = 0; ks < 4; ks++) {
        int k = ks * 8;
        uint32_t af[4][4], bf[4][2];
#pragma unroll
        for (int mi = 0; mi < 4; mi++) {
            int mb = warp_m + mi * 16;
            af[mi][0] = Au[swidx(mb + g,     k + t)];
            af[mi][1] = Au[swidx(mb + g + 8, k + t)];
            af[mi][2] = Au[swidx(mb + g,     k + t + 4)];
            af[mi][3] = Au[swidx(mb + g + 8, k + t + 4)];
        }
#pragma unroll
        for (int ni = 0; ni < 4; ni++) {
            int nb = warp_n + ni * 8;
            bf[ni][0] = Bu[swidx(nb + g, k + t)];
            bf[ni][1] = Bu[swidx(nb + g, k + t + 4)];
        }
#pragma unroll
        for (int mi = 0; mi < 4; mi++)
#pragma unroll
            for (int ni = 0; ni < 4; ni++)
                mma8(acc[mi][ni], af[mi], bf[ni]);
    }
}

// ---------------- K1: 1x1 convs -> top/center bf16 hi+lo [B][HW][P] ----------
__global__ void k_top_center(const float* __restrict__ x,
                             const float* __restrict__ wt, const float* __restrict__ bt,
                             const float* __restrict__ wc, const float* __restrict__ bc)
{
    const int b  = blockIdx.y;
    const int n0 = blockIdx.x * 64;
    const int t  = threadIdx.x;
    const int p  = t & 63;
    const int q  = t >> 6;

    __shared__ float xs[16][64];
    __shared__ float wts[64][17];
    __shared__ float wcs[64][17];

    float acct[16], accc[16];
#pragma unroll
    for (int j = 0; j < 16; j++) { acct[j] = 0.f; accc[j] = 0.f; }

    const float* xb = x + (size_t)b * CC * HWS;

    for (int c0 = 0; c0 < CC; c0 += 16) {
        {
            int cc = t >> 4;
            int nn = (t & 15) * 4;
            float4 v = *(const float4*)(xb + (size_t)(c0 + cc) * HWS + n0 + nn);
            *(float4*)&xs[cc][nn] = v;
        }
        {
            int p_ = t >> 2;
            int cq = (t & 3) * 4;
            float4 v = *(const float4*)(wt + (size_t)p_ * CC + c0 + cq);
            wts[p_][cq + 0] = v.x; wts[p_][cq + 1] = v.y; wts[p_][cq + 2] = v.z; wts[p_][cq + 3] = v.w;
            float4 u = *(const float4*)(wc + (size_t)p_ * CC + c0 + cq);
            wcs[p_][cq + 0] = u.x; wcs[p_][cq + 1] = u.y; wcs[p_][cq + 2] = u.z; wcs[p_][cq + 3] = u.w;
        }
        __syncthreads();
#pragma unroll
        for (int cc = 0; cc < 16; cc++) {
            float at = wts[p][cc];
            float ac = wcs[p][cc];
#pragma unroll
            for (int j = 0; j < 16; j++) {
                float xv = xs[cc][q * 16 + j];
                acct[j] += at * xv;
                accc[j] += ac * xv;
            }
        }
        __syncthreads();
    }

    const float btv = bt[p];
    const float bcv = bc[p];
    size_t base = (size_t)b * HWS * PP + (size_t)(n0 + q * 16) * PP + p;
#pragma unroll
    for (int j = 0; j < 16; j++) {
        float vt = acct[j] + btv;
        float vcv = accc[j] + bcv;
        __nv_bfloat16 th = __float2bfloat16(vt);
        __nv_bfloat16 tl = __float2bfloat16(vt - __bfloat162float(th));
        __nv_bfloat16 ch = __float2bfloat16(vcv);
        __nv_bfloat16 cl = __float2bfloat16(vcv - __bfloat162float(ch));
        size_t o = base + (size_t)j * PP;
        g_topH[o] = th; g_topL[o] = tl;
        g_cenH[o] = ch; g_cenL[o] = cl;
    }
}

// ---------------- conv 3x3 as tf32 implicit GEMM (register-prefetch) ---------
template<bool ADDZ>
__global__ void __launch_bounds__(256, 2)
k_conv_t(const float* __restrict__ xin, const float* __restrict__ wgt,
         const float* __restrict__ bias, float* __restrict__ outp)
{
    __shared__ float As[4096];
    __shared__ float Bs[4096];

    const int b   = blockIdx.z;
    const int n0  = blockIdx.x * 128;
    const int m0  = blockIdx.y * 128;
    const int tid = threadIdx.x;
    const int wid = tid >> 5, lane = tid & 31;
    const int warp_m = (wid & 1) * 64;
    const int warp_n = (wid >> 1) * 32;

    const float* xb = xin + (size_t)b * CC * HWS;
    const float* zb = ADDZ ? (g_attn + (size_t)b * HWS * CC) : (const float*)0;
    const float* wrow = wgt + (size_t)m0 * 2304;

    float acc[4][4][4];
#pragma unroll
    for (int mi = 0; mi < 4; mi++)
#pragma unroll
        for (int ni = 0; ni < 4; ni++)
#pragma unroll
            for (int e = 0; e < 4; e++) acc[mi][ni][e] = 0.f;

    RT ra = fetchK(wrow, 2304, 0);
    RT rb = fetchIm2col<ADDZ>(xb, zb, n0, 0);

    for (int c = 0; c < 72; c++) {
        commitP(As, ra);
        commitP(Bs, rb);
        __syncthreads();
        if (c + 1 < 72) {
            ra = fetchK(wrow, 2304, (c + 1) * 32);
            rb = fetchIm2col<ADDZ>(xb, zb, n0, (c + 1) * 32);
        }
        panel_mma(acc, As, Bs, warp_m, warp_n, lane);
        __syncthreads();
    }

    const int g = lane >> 2, t = lane & 3;
    float* obase;
    if (ADDZ) obase = outp + (size_t)b * CC * HWS;
    else      obase = g_bottomT + (size_t)b * CC * HWS;

#pragma unroll
    for (int mi = 0; mi < 4; mi++) {
        int m1 = m0 + warp_m + mi * 16 + g;
        int m2 = m1 + 8;
        float bv1 = bias[m1], bv2 = bias[m2];
#pragma unroll
        for (int ni = 0; ni < 4; ni++) {
            int n = n0 + warp_n + ni * 8 + 2 * t;
            *(float2*)(obase + (size_t)m1 * HWS + n) =
                make_float2(acc[mi][ni][0] + bv1, acc[mi][ni][1] + bv1);
            *(float2*)(obase + (size_t)m2 * HWS + n) =
                make_float2(acc[mi][ni][2] + bv2, acc[mi][ni][3] + bv2);
        }
    }
}

// ---------------- S = cen @ top^T (bf16 hi/lo x3) + fused exp/sum ------------
__global__ void __launch_bounds__(256, 1) k_S_bf16()
{
    extern __shared__ uint32_t dynS[];
    uint32_t* Ah = dynS;            // [128][32] u32 (= 64 bf16 per row)
    uint32_t* Al = dynS + 4096;
    uint32_t* Bh = dynS + 8192;
    uint32_t* Bl = dynS + 12288;
    __shared__ float red[256];

    const int b   = blockIdx.z;
    const int n0  = blockIdx.x * 128;
    const int m0  = blockIdx.y * 128;
    const int tid = threadIdx.x;
    const int wid = tid >> 5, lane = tid & 31;
    const int warp_m = (wid & 1) * 64;
    const int warp_n = (wid >> 1) * 32;
    const int g = lane >> 2, t = lane & 3;

    // ---- single-shot panel load (K = 64 entirely resident) ----
    {
        int r   = tid >> 1;
        int cb4 = (tid & 1) * 4;
        size_t rowA = ((size_t)b * HWS + m0 + r) * PP;
        size_t rowB = ((size_t)b * HWS + n0 + r) * PP;
        const uint4* sAh = (const uint4*)(g_cenH + rowA);
        const uint4* sAl = (const uint4*)(g_cenL + rowA);
        const uint4* sBh = (const uint4*)(g_topH + rowB);
        const uint4* sBl = (const uint4*)(g_topL + rowB);
#pragma unroll
        for (int j = 0; j < 4; j++) {
            int c = cb4 + j;
            int d = r * 32 + ((c ^ (r & 7)) << 2);
            *(uint4*)&Ah[d] = sAh[c];
            *(uint4*)&Al[d] = sAl[c];
            *(uint4*)&Bh[d] = sBh[c];
            *(uint4*)&Bl[d] = sBl[c];
        }
    }
    __syncthreads();

    float acc[4][4][4];
#pragma unroll
    for (int mi = 0; mi < 4; mi++)
#pragma unroll
        for (int ni = 0; ni < 4; ni++)
#pragma unroll
            for (int e = 0; e < 4; e++) acc[mi][ni][e] = 0.f;

#pragma unroll
    for (int ks = 0; ks < 4; ks++) {
        int p = ks * 8;   // pair-column base (16 bf16 per kstep)
        uint32_t ah[4][4], al[4][4], bh[4][2], bl[4][2];
#pragma unroll
        for (int mi = 0; mi < 4; mi++) {
            int mb = warp_m + mi * 16;
            ah[mi][0] = Ah[swidx(mb + g,     p + t)];
            ah[mi][1] = Ah[swidx(mb + g + 8, p + t)];
            ah[mi][2] = Ah[swidx(mb + g,     p + t + 4)];
            ah[mi][3] = Ah[swidx(mb + g + 8, p + t + 4)];
            al[mi][0] = Al[swidx(mb + g,     p + t)];
            al[mi][1] = Al[swidx(mb + g + 8, p + t)];
            al[mi][2] = Al[swidx(mb + g,     p + t + 4)];
            al[mi][3] = Al[swidx(mb + g + 8, p + t + 4)];
        }
#pragma unroll
        for (int ni = 0; ni < 4; ni++) {
            int nb = warp_n + ni * 8;
            bh[ni][0] = Bh[swidx(nb + g, p + t)];
            bh[ni][1] = Bh[swidx(nb + g, p + t + 4)];
            bl[ni][0] = Bl[swidx(nb + g, p + t)];
            bl[ni][1] = Bl[swidx(nb + g, p + t + 4)];
        }
#pragma unroll
        for (int mi = 0; mi < 4; mi++)
#pragma unroll
            for (int ni = 0; ni < 4; ni++) {
                mma16bf(acc[mi][ni], ah[mi], bh[ni]);
                mma16bf(acc[mi][ni], ah[mi], bl[ni]);
                mma16bf(acc[mi][ni], al[mi], bh[ni]);
            }
    }

    // ---- epilogue: E = exp(S - 40), write, deterministic partial sum ----
    float* Eb = g_S + (size_t)b * HWS * HWS;
    float ls = 0.f;
#pragma unroll
    for (int mi = 0; mi < 4; mi++) {
        int m1 = m0 + warp_m + mi * 16 + g;
        int m2 = m1 + 8;
#pragma unroll
        for (int ni = 0; ni < 4; ni++) {
            int n = n0 + warp_n + ni * 8 + 2 * t;
            float e0 = __expf(acc[mi][ni][0] - 40.f);
            float e1 = __expf(acc[mi][ni][1] - 40.f);
            float e2 = __expf(acc[mi][ni][2] - 40.f);
            float e3 = __expf(acc[mi][ni][3] - 40.f);
            ls += (e0 + e1) + (e2 + e3);
            *(float2*)(Eb + (size_t)m1 * HWS + n) = make_float2(e0, e1);
            *(float2*)(Eb + (size_t)m2 * HWS + n) = make_float2(e2, e3);
        }
    }
    red[tid] = ls;
    __syncthreads();
    for (int st = 128; st > 0; st >>= 1) {
        if (tid < st) red[tid] += red[tid + st];
        __syncthreads();
    }
    if (tid == 0) g_partialS[b * 1024 + blockIdx.y * 32 + blockIdx.x] = red[0];
}

// ---------------- reduce partial sums ----------------------------------------
__global__ void k_sumreduce()
{
    const int b = blockIdx.x;
    const int tid = threadIdx.x;
    __shared__ float red[256];
    float s = 0.f;
    for (int i = tid; i < 1024; i += 256) s += g_partialS[b * 1024 + i];
    red[tid] = s;
    __syncthreads();
    for (int st = 128; st > 0; st >>= 1) {
        if (tid < st) red[tid] += red[tid + st];
        __syncthreads();
    }
    if (tid == 0) g_sum[b] = red[0];
}

// ---------------- attn = (E/sum) @ bottomT^T (register-prefetch) -------------
__global__ void __launch_bounds__(256, 2) k_attn_t()
{
    __shared__ float As[4096];
    __shared__ float Bs[4096];

    const int b   = blockIdx.z;
    const int cb  = blockIdx.x * 128;   // C tile
    const int m0  = blockIdx.y * 128;   // HW tile
    const int tid = threadIdx.x;
    const int wid = tid >> 5, lane = tid & 31;
    const int warp_m = (wid & 1) * 64;
    const int warp_n = (wid >> 1) * 32;

    const float* A  = g_S       + (size_t)b * HWS * HWS + (size_t)m0 * HWS;
    const float* Bt = g_bottomT + (size_t)b * CC * HWS + (size_t)cb * HWS;

    float acc[4][4][4];
#pragma unroll
    for (int mi = 0; mi < 4; mi++)
#pragma unroll
        for (int ni = 0; ni < 4; ni++)
#pragma unroll
            for (int e = 0; e < 4; e++) acc[mi][ni][e] = 0.f;

    RT ra = fetchK(A,  HWS, 0);
    RT rb = fetchK(Bt, HWS, 0);

    for (int c = 0; c < 128; c++) {
        commitP(As, ra);
        commitP(Bs, rb);
        __syncthreads();
        if (c + 1 < 128) {
            ra = fetchK(A,  HWS, (c + 1) * 32);
            rb = fetchK(Bt, HWS, (c + 1) * 32);
        }
        panel_mma(acc, As, Bs, warp_m, warp_n, lane);
        __syncthreads();
    }

    const int g = lane >> 2, t = lane & 3;
    const float inv = 1.0f / g_sum[b];
    float* obase = g_attn + (size_t)b * HWS * CC;

#pragma unroll
    for (int mi = 0; mi < 4; mi++) {
        int m1 = m0 + warp_m + mi * 16 + g;
        int m2 = m1 + 8;
#pragma unroll
        for (int ni = 0; ni < 4; ni++) {
            int n = cb + warp_n + ni * 8 + 2 * t;
            *(float2*)(obase + (size_t)m1 * CC + n) =
                make_float2(acc[mi][ni][0] * inv, acc[mi][ni][1] * inv);
            *(float2*)(obase + (size_t)m2 * CC + n) =
                make_float2(acc[mi][ni][2] * inv, acc[mi][ni][3] * inv);
        }
    }
}

// ---------------- launch -----------------------------------------------------
extern "C" void kernel_launch(void* const* d_in, const int* in_sizes, int n_in,
                              void* d_out, int out_size)
{
    const float* x   = (const float*)d_in[0];
    const float* wt  = (const float*)d_in[1];
    const float* bt  = (const float*)d_in[2];
    const float* wc  = (const float*)d_in[3];
    const float* bc  = (const float*)d_in[4];
    const float* wb  = (const float*)d_in[5];
    const float* bbm = (const float*)d_in[6];
    const float* wo  = (const float*)d_in[7];
    const float* bo  = (const float*)d_in[8];
    float* out = (float*)d_out;

    cudaFuncSetAttribute(k_S_bf16, cudaFuncAttributeMaxDynamicSharedMemorySize, 65536);

    k_top_center<<<dim3(HWS / 64, BB), 256>>>(x, wt, bt, wc, bc);
    k_conv_t<false><<<dim3(32, 2, BB), 256>>>(x, wb, bbm, nullptr);
    k_S_bf16<<<dim3(32, 32, BB), 256, 65536>>>();
    k_sumreduce<<<BB, 256>>>();
    k_attn_t<<<dim3(2, 32, BB), 256>>>();
    k_conv_t<true><<<dim3(32, 2, BB), 256>>>(x, wo, bo, out);
}

// round 9
// speedup vs baseline: 1.2428x; 1.2428x over previous
#include <cuda_runtime.h>
#include <cstdint>

#define BB  8
#define CC  256
#define PP  64
#define HWS 4096

// ---------------- scratch (device globals) ----------------------------------
__device__ __align__(128) float g_xr [BB * CC * HWS];     // tf32-rounded x
__device__ __align__(128) float g_xz [BB * CC * HWS];     // tf32-rounded x + attn (flat reinterp)
__device__ __align__(128) float g_wbr[CC * 2304];         // rounded w_bottom
__device__ __align__(128) float g_wor[CC * 2304];         // rounded w_out
__device__ __align__(128) float g_topH[BB * HWS * PP];    // tf32 hi ([B][HW][P])
__device__ __align__(128) float g_topL[BB * HWS * PP];    // tf32 lo
__device__ __align__(128) float g_cenH[BB * HWS * PP];
__device__ __align__(128) float g_cenL[BB * HWS * PP];
__device__ __align__(128) float g_bottomT[BB * CC * HWS]; // rounded [B][C][HW]
__device__ __align__(128) float g_S[134217728];           // [B][HW][HW]; holds rounded E
__device__ float g_partialS[BB * 1024];
__device__ float g_sum[BB];

// ---------------- helpers ----------------------------------------------------
__device__ __forceinline__ float tf32r(float x) {
    uint32_t u;
    asm("cvt.rna.tf32.f32 %0, %1;" : "=r"(u) : "f"(x));
    return __uint_as_float(u);
}

__device__ __forceinline__ void mma8(float* d, const uint32_t* a, const uint32_t* b) {
    asm volatile(
        "mma.sync.aligned.m16n8k8.row.col.f32.tf32.tf32.f32 "
        "{%0,%1,%2,%3}, {%4,%5,%6,%7}, {%8,%9}, {%0,%1,%2,%3};"
        : "+f"(d[0]), "+f"(d[1]), "+f"(d[2]), "+f"(d[3])
        : "r"(a[0]), "r"(a[1]), "r"(a[2]), "r"(a[3]), "r"(b[0]), "r"(b[1]));
}

__device__ __forceinline__ int swidx(int r, int k) {
    return r * 32 + (((k >> 2) ^ (r & 7)) << 2) + (k & 3);
}

__device__ __forceinline__ uint32_t s2u(const void* p) {
    uint32_t a;
    asm("{ .reg .u64 t; cvta.to.shared.u64 t, %1; cvt.u32.u64 %0, t; }" : "=r"(a) : "l"(p));
    return a;
}

__device__ __forceinline__ void cpa16(uint32_t dst, const void* src) {
    asm volatile("cp.async.cg.shared.global [%0], [%1], 16;" :: "r"(dst), "l"(src));
}
#define CP_COMMIT() asm volatile("cp.async.commit_group;" ::: "memory")
#define CP_WAIT(N)  asm volatile("cp.async.wait_group %0;" :: "n"(N) : "memory")

// ---------------- panel loaders (256 threads, panel = 128 x 32) --------------
// plain contiguous copy (pre-rounded data), swizzled STS
__device__ __forceinline__ void load_panel_copy(float* pan, const float* src, int lda, int k0) {
    int r  = threadIdx.x >> 1;
    int kq = (threadIdx.x & 1) * 4;
    const float4* row = (const float4*)(src + (size_t)r * lda + k0) + kq;
#pragma unroll
    for (int j = 0; j < 4; j++)
        *(float4*)&pan[r * 32 + (((kq + j) ^ (r & 7)) << 2)] = row[j];
}

// im2col gather from pre-rounded source (no add, no cvt)
__device__ __forceinline__ void load_panel_gather(float* pan, const float* __restrict__ src,
                                                  int n0, int k0) {
    int r  = threadIdx.x >> 1;
    int kq = (threadIdx.x & 1) * 4;
    int n  = n0 + r;
    int h  = n >> 6, w = n & 63;
    int kbase = k0 + kq * 4;
    int ci = kbase / 9;
    int rr = kbase - ci * 9;
#pragma unroll
    for (int j = 0; j < 4; j++) {
        float vv[4];
#pragma unroll
        for (int e = 0; e < 4; e++) {
            int dh = rr / 3 - 1;
            int dw = rr - (rr / 3) * 3 - 1;
            int hh = h + dh, ww = w + dw;
            float v = 0.f;
            if ((unsigned)hh < 64u && (unsigned)ww < 64u)
                v = src[ci * HWS + hh * 64 + ww];
            vv[e] = v;
            if (++rr == 9) { rr = 0; ci++; }
        }
        *(float4*)&pan[r * 32 + (((kq + j) ^ (r & 7)) << 2)] =
            make_float4(vv[0], vv[1], vv[2], vv[3]);
    }
}

// cp.async issue of one 128x32 panel pair (contiguous K-major rows)
__device__ __forceinline__ void issue_pair(uint32_t smA, uint32_t smB,
                                           const float* A, const float* B, int k0) {
    int r  = threadIdx.x >> 1;
    int kq = (threadIdx.x & 1) * 4;
    const float* arow = A + (size_t)r * HWS + k0;
    const float* brow = B + (size_t)r * HWS + k0;
#pragma unroll
    for (int j = 0; j < 4; j++) {
        uint32_t off = (uint32_t)((r * 32 + (((kq + j) ^ (r & 7)) << 2)) * 4);
        cpa16(smA + off, arow + (kq + j) * 4);
        cpa16(smB + off, brow + (kq + j) * 4);
    }
}

__device__ __forceinline__ void issue_one(uint32_t smA, const float* A, int lda, int k0) {
    int r  = threadIdx.x >> 1;
    int kq = (threadIdx.x & 1) * 4;
    const float* arow = A + (size_t)r * lda + k0;
#pragma unroll
    for (int j = 0; j < 4; j++) {
        uint32_t off = (uint32_t)((r * 32 + (((kq + j) ^ (r & 7)) << 2)) * 4);
        cpa16(smA + off, arow + (kq + j) * 4);
    }
}

// ---------------- warp compute over one k32 tf32 panel -----------------------
__device__ __forceinline__ void panel_mma(float acc[4][4][4],
                                          const float* As, const float* Bs,
                                          int warp_m, int warp_n, int lane) {
    const uint32_t* Au = (const uint32_t*)As;
    const uint32_t* Bu = (const uint32_t*)Bs;
    int g = lane >> 2, t = lane & 3;
#pragma unroll
    for (int ks = 0; ks < 4; ks++) {
        int k = ks * 8;
        uint32_t af[4][4], bf[4][2];
#pragma unroll
        for (int mi = 0; mi < 4; mi++) {
            int mb = warp_m + mi * 16;
            af[mi][0] = Au[swidx(mb + g,     k + t)];
            af[mi][1] = Au[swidx(mb + g + 8, k + t)];
            af[mi][2] = Au[swidx(mb + g,     k + t + 4)];
            af[mi][3] = Au[swidx(mb + g + 8, k + t + 4)];
        }
#pragma unroll
        for (int ni = 0; ni < 4; ni++) {
            int nb = warp_n + ni * 8;
            bf[ni][0] = Bu[swidx(nb + g, k + t)];
            bf[ni][1] = Bu[swidx(nb + g, k + t + 4)];
        }
#pragma unroll
        for (int mi = 0; mi < 4; mi++)
#pragma unroll
            for (int ni = 0; ni < 4; ni++)
                mma8(acc[mi][ni], af[mi], bf[ni]);
    }
}

// ---------------- K0: tf32 pre-round ----------------------------------------
__global__ void k_round(const float* __restrict__ s, float* __restrict__ d, int n) {
    int i = blockIdx.x * 256 + threadIdx.x;
    if (i < n) d[i] = tf32r(s[i]);
}

// ---------------- K1: 1x1 convs -> top/center tf32 hi+lo [B][HW][P] ----------
__global__ void k_top_center(const float* __restrict__ x,
                             const float* __restrict__ wt, const float* __restrict__ bt,
                             const float* __restrict__ wc, const float* __restrict__ bc)
{
    const int b  = blockIdx.y;
    const int n0 = blockIdx.x * 64;
    const int t  = threadIdx.x;
    const int p  = t & 63;
    const int q  = t >> 6;

    __shared__ float xs[16][64];
    __shared__ float wts[64][17];
    __shared__ float wcs[64][17];

    float acct[16], accc[16];
#pragma unroll
    for (int j = 0; j < 16; j++) { acct[j] = 0.f; accc[j] = 0.f; }

    const float* xb = x + (size_t)b * CC * HWS;

    for (int c0 = 0; c0 < CC; c0 += 16) {
        {
            int cc = t >> 4;
            int nn = (t & 15) * 4;
            float4 v = *(const float4*)(xb + (size_t)(c0 + cc) * HWS + n0 + nn);
            *(float4*)&xs[cc][nn] = v;
        }
        {
            int p_ = t >> 2;
            int cq = (t & 3) * 4;
            float4 v = *(const float4*)(wt + (size_t)p_ * CC + c0 + cq);
            wts[p_][cq + 0] = v.x; wts[p_][cq + 1] = v.y; wts[p_][cq + 2] = v.z; wts[p_][cq + 3] = v.w;
            float4 u = *(const float4*)(wc + (size_t)p_ * CC + c0 + cq);
            wcs[p_][cq + 0] = u.x; wcs[p_][cq + 1] = u.y; wcs[p_][cq + 2] = u.z; wcs[p_][cq + 3] = u.w;
        }
        __syncthreads();
#pragma unroll
        for (int cc = 0; cc < 16; cc++) {
            float at = wts[p][cc];
            float ac = wcs[p][cc];
#pragma unroll
            for (int j = 0; j < 16; j++) {
                float xv = xs[cc][q * 16 + j];
                acct[j] += at * xv;
                accc[j] += ac * xv;
            }
        }
        __syncthreads();
    }

    const float btv = bt[p];
    const float bcv = bc[p];
    size_t base = (size_t)b * HWS * PP + (size_t)(n0 + q * 16) * PP + p;
#pragma unroll
    for (int j = 0; j < 16; j++) {
        float vt = acct[j] + btv;
        float vc = accc[j] + bcv;
        float th = tf32r(vt), tl = tf32r(vt - th);
        float ch = tf32r(vc), cl = tf32r(vc - ch);
        size_t o = base + (size_t)j * PP;
        g_topH[o] = th; g_topL[o] = tl;
        g_cenH[o] = ch; g_cenL[o] = cl;
    }
}

// ---------------- conv 3x3 as tf32 implicit GEMM -----------------------------
template<bool ADDZ>
__global__ void __launch_bounds__(256, 2)
k_conv_t(const float* __restrict__ bias, float* __restrict__ outp)
{
    __shared__ float As[4096];
    __shared__ float Bs[4096];

    const int b   = blockIdx.z;
    const int n0  = blockIdx.x * 128;
    const int m0  = blockIdx.y * 128;
    const int tid = threadIdx.x;
    const int wid = tid >> 5, lane = tid & 31;
    const int warp_m = (wid & 1) * 64;
    const int warp_n = (wid >> 1) * 32;

    const float* srcB = (ADDZ ? g_xz : g_xr) + (size_t)b * CC * HWS;
    const float* wrow = (ADDZ ? g_wor : g_wbr) + (size_t)m0 * 2304;
    const uint32_t smA = s2u(As);

    float acc[4][4][4];
#pragma unroll
    for (int mi = 0; mi < 4; mi++)
#pragma unroll
        for (int ni = 0; ni < 4; ni++)
#pragma unroll
            for (int e = 0; e < 4; e++) acc[mi][ni][e] = 0.f;

    for (int c = 0; c < 72; c++) {
        __syncthreads();
        issue_one(smA, wrow, 2304, c * 32);          // async weight panel
        load_panel_gather(Bs, srcB, n0, c * 32);     // scalar im2col (overlaps A copy)
        CP_COMMIT();
        CP_WAIT(0);
        __syncthreads();
        panel_mma(acc, As, Bs, warp_m, warp_n, lane);
    }

    const int g = lane >> 2, t = lane & 3;
    float* obase = ADDZ ? outp + (size_t)b * CC * HWS
                        : g_bottomT + (size_t)b * CC * HWS;

#pragma unroll
    for (int mi = 0; mi < 4; mi++) {
        int m1 = m0 + warp_m + mi * 16 + g;
        int m2 = m1 + 8;
        float bv1 = bias[m1], bv2 = bias[m2];
#pragma unroll
        for (int ni = 0; ni < 4; ni++) {
            int n = n0 + warp_n + ni * 8 + 2 * t;
            if (ADDZ) {
                *(float2*)(obase + (size_t)m1 * HWS + n) =
                    make_float2(acc[mi][ni][0] + bv1, acc[mi][ni][1] + bv1);
                *(float2*)(obase + (size_t)m2 * HWS + n) =
                    make_float2(acc[mi][ni][2] + bv2, acc[mi][ni][3] + bv2);
            } else {
                *(float2*)(obase + (size_t)m1 * HWS + n) =
                    make_float2(tf32r(acc[mi][ni][0] + bv1), tf32r(acc[mi][ni][1] + bv1));
                *(float2*)(obase + (size_t)m2 * HWS + n) =
                    make_float2(tf32r(acc[mi][ni][2] + bv2), tf32r(acc[mi][ni][3] + bv2));
            }
        }
    }
}

// ---------------- S = cen @ top^T (tf32 hi/lo x3) + fused exp/sum ------------
__global__ void __launch_bounds__(256, 1) k_S_t()
{
    extern __shared__ float dyn[];
    float* Ah = dyn;
    float* Al = dyn + 4096;
    float* Bh = dyn + 8192;
    float* Bl = dyn + 12288;
    __shared__ float red[256];

    const int b   = blockIdx.z;
    const int n0  = blockIdx.x * 128;
    const int m0  = blockIdx.y * 128;
    const int tid = threadIdx.x;
    const int wid = tid >> 5, lane = tid & 31;
    const int warp_m = (wid & 1) * 64;
    const int warp_n = (wid >> 1) * 32;
    const int g = lane >> 2, t = lane & 3;

    const int r  = tid >> 1;
    const int kq = (tid & 1) * 4;
    const size_t rowA = ((size_t)b * HWS + m0 + r) * PP;
    const size_t rowB = ((size_t)b * HWS + n0 + r) * PP;

    float acc[4][4][4];
#pragma unroll
    for (int mi = 0; mi < 4; mi++)
#pragma unroll
        for (int ni = 0; ni < 4; ni++)
#pragma unroll
            for (int e = 0; e < 4; e++) acc[mi][ni][e] = 0.f;

    const uint32_t* Ahu = (const uint32_t*)Ah;
    const uint32_t* Alu = (const uint32_t*)Al;
    const uint32_t* Bhu = (const uint32_t*)Bh;
    const uint32_t* Blu = (const uint32_t*)Bl;

    for (int c = 0; c < 2; c++) {
        __syncthreads();
        {
            const float4* pAh = (const float4*)(g_cenH + rowA);
            const float4* pAl = (const float4*)(g_cenL + rowA);
            const float4* pBh = (const float4*)(g_topH + rowB);
            const float4* pBl = (const float4*)(g_topL + rowB);
#pragma unroll
            for (int j = 0; j < 4; j++) {
                int sc = c * 8 + kq + j;
                int d  = r * 32 + (((kq + j) ^ (r & 7)) << 2);
                *(float4*)&Ah[d] = pAh[sc];
                *(float4*)&Al[d] = pAl[sc];
                *(float4*)&Bh[d] = pBh[sc];
                *(float4*)&Bl[d] = pBl[sc];
            }
        }
        __syncthreads();
#pragma unroll
        for (int ks = 0; ks < 4; ks++) {
            int k = ks * 8;
            uint32_t ah[4][4], al[4][4], bh[4][2], bl[4][2];
#pragma unroll
            for (int mi = 0; mi < 4; mi++) {
                int mb = warp_m + mi * 16;
                ah[mi][0] = Ahu[swidx(mb + g,     k + t)];
                ah[mi][1] = Ahu[swidx(mb + g + 8, k + t)];
                ah[mi][2] = Ahu[swidx(mb + g,     k + t + 4)];
                ah[mi][3] = Ahu[swidx(mb + g + 8, k + t + 4)];
                al[mi][0] = Alu[swidx(mb + g,     k + t)];
                al[mi][1] = Alu[swidx(mb + g + 8, k + t)];
                al[mi][2] = Alu[swidx(mb + g,     k + t + 4)];
                al[mi][3] = Alu[swidx(mb + g + 8, k + t + 4)];
            }
#pragma unroll
            for (int ni = 0; ni < 4; ni++) {
                int nb = warp_n + ni * 8;
                bh[ni][0] = Bhu[swidx(nb + g, k + t)];
                bh[ni][1] = Bhu[swidx(nb + g, k + t + 4)];
                bl[ni][0] = Blu[swidx(nb + g, k + t)];
                bl[ni][1] = Blu[swidx(nb + g, k + t + 4)];
            }
#pragma unroll
            for (int mi = 0; mi < 4; mi++)
#pragma unroll
                for (int ni = 0; ni < 4; ni++) {
                    mma8(acc[mi][ni], ah[mi], bh[ni]);
                    mma8(acc[mi][ni], ah[mi], bl[ni]);
                    mma8(acc[mi][ni], al[mi], bh[ni]);
                }
        }
    }

    // epilogue: E = tf32r(exp(S - 40)); sum the ROUNDED values (consistent softmax)
    float* Eb = g_S + (size_t)b * HWS * HWS;
    float ls = 0.f;
#pragma unroll
    for (int mi = 0; mi < 4; mi++) {
        int m1 = m0 + warp_m + mi * 16 + g;
        int m2 = m1 + 8;
#pragma unroll
        for (int ni = 0; ni < 4; ni++) {
            int n = n0 + warp_n + ni * 8 + 2 * t;
            float e0 = tf32r(__expf(acc[mi][ni][0] - 40.f));
            float e1 = tf32r(__expf(acc[mi][ni][1] - 40.f));
            float e2 = tf32r(__expf(acc[mi][ni][2] - 40.f));
            float e3 = tf32r(__expf(acc[mi][ni][3] - 40.f));
            ls += (e0 + e1) + (e2 + e3);
            *(float2*)(Eb + (size_t)m1 * HWS + n) = make_float2(e0, e1);
            *(float2*)(Eb + (size_t)m2 * HWS + n) = make_float2(e2, e3);
        }
    }
    red[tid] = ls;
    __syncthreads();
    for (int st = 128; st > 0; st >>= 1) {
        if (tid < st) red[tid] += red[tid + st];
        __syncthreads();
    }
    if (tid == 0) g_partialS[b * 1024 + blockIdx.y * 32 + blockIdx.x] = red[0];
}

// ---------------- reduce partial sums ----------------------------------------
__global__ void k_sumreduce()
{
    const int b = blockIdx.x;
    const int tid = threadIdx.x;
    __shared__ float red[256];
    float s = 0.f;
    for (int i = tid; i < 1024; i += 256) s += g_partialS[b * 1024 + i];
    red[tid] = s;
    __syncthreads();
    for (int st = 128; st > 0; st >>= 1) {
        if (tid < st) red[tid] += red[tid + st];
        __syncthreads();
    }
    if (tid == 0) g_sum[b] = red[0];
}

// ---------------- attn: (E/sum)@bottomT^T, cp.async 2-stage; writes x+attn ---
__global__ void __launch_bounds__(256, 2) k_attn_cp(const float* __restrict__ x)
{
    extern __shared__ float sm[];   // 2 x (A 4096 + B 4096) floats = 64KB
    const uint32_t smb = s2u(sm);

    const int b   = blockIdx.z;
    const int cb  = blockIdx.x * 128;   // C tile
    const int m0  = blockIdx.y * 128;   // HW tile
    const int tid = threadIdx.x;
    const int wid = tid >> 5, lane = tid & 31;
    const int warp_m = (wid & 1) * 64;
    const int warp_n = (wid >> 1) * 32;

    const float* A  = g_S       + (size_t)b * HWS * HWS + (size_t)m0 * HWS;
    const float* Bt = g_bottomT + (size_t)b * CC * HWS + (size_t)cb * HWS;

    float acc[4][4][4];
#pragma unroll
    for (int mi = 0; mi < 4; mi++)
#pragma unroll
        for (int ni = 0; ni < 4; ni++)
#pragma unroll
            for (int e = 0; e < 4; e++) acc[mi][ni][e] = 0.f;

    issue_pair(smb, smb + 16384, A, Bt, 0);
    CP_COMMIT();

    for (int c = 0; c < 128; c++) {
        int cur = c & 1;
        if (c < 127) {
            uint32_t nb = smb + (cur ^ 1) * 32768;
            issue_pair(nb, nb + 16384, A, Bt, (c + 1) * 32);
            CP_COMMIT();
            CP_WAIT(1);
        } else {
            CP_WAIT(0);
        }
        __syncthreads();
        panel_mma(acc, sm + cur * 8192, sm + cur * 8192 + 4096, warp_m, warp_n, lane);
        __syncthreads();
    }

    const int g = lane >> 2, t = lane & 3;
    const float inv = 1.0f / g_sum[b];
    const float* xb = x + (size_t)b * CC * HWS;
    float* zb = g_xz + (size_t)b * CC * HWS;

#pragma unroll
    for (int mi = 0; mi < 4; mi++) {
        int m1 = m0 + warp_m + mi * 16 + g;
        int m2 = m1 + 8;
#pragma unroll
        for (int ni = 0; ni < 4; ni++) {
            int n = cb + warp_n + ni * 8 + 2 * t;
            int f1 = m1 * CC + n;
            int f2 = m2 * CC + n;
            float2 x1 = *(const float2*)(xb + f1);
            float2 x2 = *(const float2*)(xb + f2);
            *(float2*)(zb + f1) = make_float2(tf32r(x1.x + acc[mi][ni][0] * inv),
                                              tf32r(x1.y + acc[mi][ni][1] * inv));
            *(float2*)(zb + f2) = make_float2(tf32r(x2.x + acc[mi][ni][2] * inv),
                                              tf32r(x2.y + acc[mi][ni][3] * inv));
        }
    }
}

// ---------------- launch -----------------------------------------------------
extern "C" void kernel_launch(void* const* d_in, const int* in_sizes, int n_in,
                              void* d_out, int out_size)
{
    const float* x   = (const float*)d_in[0];
    const float* wt  = (const float*)d_in[1];
    const float* bt  = (const float*)d_in[2];
    const float* wc  = (const float*)d_in[3];
    const float* bc  = (const float*)d_in[4];
    const float* wb  = (const float*)d_in[5];
    const float* bbm = (const float*)d_in[6];
    const float* wo  = (const float*)d_in[7];
    const float* bo  = (const float*)d_in[8];
    float* out = (float*)d_out;

    cudaFuncSetAttribute(k_S_t,     cudaFuncAttributeMaxDynamicSharedMemorySize, 65536);
    cudaFuncSetAttribute(k_attn_cp, cudaFuncAttributeMaxDynamicSharedMemorySize, 65536);

    float* d_xr;  cudaGetSymbolAddress((void**)&d_xr,  g_xr);
    float* d_wbr; cudaGetSymbolAddress((void**)&d_wbr, g_wbr);
    float* d_wor; cudaGetSymbolAddress((void**)&d_wor, g_wor);

    k_round<<<(BB * CC * HWS + 255) / 256, 256>>>(x,  d_xr,  BB * CC * HWS);
    k_round<<<(CC * 2304 + 255) / 256, 256>>>(wb, d_wbr, CC * 2304);
    k_round<<<(CC * 2304 + 255) / 256, 256>>>(wo, d_wor, CC * 2304);

    k_top_center<<<dim3(HWS / 64, BB), 256>>>(x, wt, bt, wc, bc);
    k_conv_t<false><<<dim3(32, 2, BB), 256>>>(bbm, nullptr);
    k_S_t<<<dim3(32, 32, BB), 256, 65536>>>();
    k_sumreduce<<<BB, 256>>>();
    k_attn_cp<<<dim3(2, 32, BB), 256, 65536>>>(x);
    k_conv_t<true><<<dim3(32, 2, BB), 256>>>(bo, out);
}

// round 10
// speedup vs baseline: 1.2469x; 1.0033x over previous
#include <cuda_runtime.h>
#include <cstdint>

#define BB  8
#define CC  256
#define PP  64
#define HWS 4096

// ---------------- scratch (device globals) ----------------------------------
__device__ __align__(128) float g_xr [BB * CC * HWS];     // tf32-rounded x
__device__ __align__(128) float g_xz [BB * CC * HWS];     // tf32-rounded x + attn (flat reinterp)
__device__ __align__(128) float g_wbr[CC * 2304];         // w_bottom reordered [co][r3][ci], tf32
__device__ __align__(128) float g_wor[CC * 2304];         // w_out reordered   [co][r3][ci], tf32
__device__ __align__(128) float g_topH[BB * HWS * PP];    // tf32 hi ([B][HW][P])
__device__ __align__(128) float g_topL[BB * HWS * PP];    // tf32 lo
__device__ __align__(128) float g_cenH[BB * HWS * PP];
__device__ __align__(128) float g_cenL[BB * HWS * PP];
__device__ __align__(128) float g_bottomT[BB * CC * HWS]; // rounded [B][C][HW]
__device__ __align__(128) float g_S[134217728];           // [B][HW][HW]; holds rounded E
__device__ float g_partialS[BB * 1024];
__device__ float g_sum[BB];

// ---------------- helpers ----------------------------------------------------
__device__ __forceinline__ float tf32r(float x) {
    uint32_t u;
    asm("cvt.rna.tf32.f32 %0, %1;" : "=r"(u) : "f"(x));
    return __uint_as_float(u);
}

__device__ __forceinline__ void mma8(float* d, const uint32_t* a, const uint32_t* b) {
    asm volatile(
        "mma.sync.aligned.m16n8k8.row.col.f32.tf32.tf32.f32 "
        "{%0,%1,%2,%3}, {%4,%5,%6,%7}, {%8,%9}, {%0,%1,%2,%3};"
        : "+f"(d[0]), "+f"(d[1]), "+f"(d[2]), "+f"(d[3])
        : "r"(a[0]), "r"(a[1]), "r"(a[2]), "r"(a[3]), "r"(b[0]), "r"(b[1]));
}

__device__ __forceinline__ int swidx(int r, int k) {
    return r * 32 + (((k >> 2) ^ (r & 7)) << 2) + (k & 3);
}

__device__ __forceinline__ uint32_t s2u(const void* p) {
    uint32_t a;
    asm("{ .reg .u64 t; cvta.to.shared.u64 t, %1; cvt.u32.u64 %0, t; }" : "=r"(a) : "l"(p));
    return a;
}

__device__ __forceinline__ void cpa16(uint32_t dst, const void* src) {
    asm volatile("cp.async.cg.shared.global [%0], [%1], 16;" :: "r"(dst), "l"(src));
}
__device__ __forceinline__ void cpa4(uint32_t dst, const void* src) {
    asm volatile("cp.async.ca.shared.global [%0], [%1], 4;" :: "r"(dst), "l"(src));
}
#define CP_COMMIT() asm volatile("cp.async.commit_group;" ::: "memory")
#define CP_WAIT(N)  asm volatile("cp.async.wait_group %0;" :: "n"(N) : "memory")

// cp.async issue of one 128x32 panel pair (contiguous K-major rows)
__device__ __forceinline__ void issue_pair(uint32_t smA, uint32_t smB,
                                           const float* A, const float* B, int k0) {
    int r  = threadIdx.x >> 1;
    int kq = (threadIdx.x & 1) * 4;
    const float* arow = A + (size_t)r * HWS + k0;
    const float* brow = B + (size_t)r * HWS + k0;
#pragma unroll
    for (int j = 0; j < 4; j++) {
        uint32_t off = (uint32_t)((r * 32 + (((kq + j) ^ (r & 7)) << 2)) * 4);
        cpa16(smA + off, arow + (kq + j) * 4);
        cpa16(smB + off, brow + (kq + j) * 4);
    }
}

// ---------------- warp compute over one k32 tf32 panel -----------------------
__device__ __forceinline__ void panel_mma(float acc[4][4][4],
                                          const float* As, const float* Bs,
                                          int warp_m, int warp_n, int lane) {
    const uint32_t* Au = (const uint32_t*)As;
    const uint32_t* Bu = (const uint32_t*)Bs;
    int g = lane >> 2, t = lane & 3;
#pragma unroll
    for (int ks = 0; ks < 4; ks++) {
        int k = ks * 8;
        uint32_t af[4][4], bf[4][2];
#pragma unroll
        for (int mi = 0; mi < 4; mi++) {
            int mb = warp_m + mi * 16;
            af[mi][0] = Au[swidx(mb + g,     k + t)];
            af[mi][1] = Au[swidx(mb + g + 8, k + t)];
            af[mi][2] = Au[swidx(mb + g,     k + t + 4)];
            af[mi][3] = Au[swidx(mb + g + 8, k + t + 4)];
        }
#pragma unroll
        for (int ni = 0; ni < 4; ni++) {
            int nb = warp_n + ni * 8;
            bf[ni][0] = Bu[swidx(nb + g, k + t)];
            bf[ni][1] = Bu[swidx(nb + g, k + t + 4)];
        }
#pragma unroll
        for (int mi = 0; mi < 4; mi++)
#pragma unroll
            for (int ni = 0; ni < 4; ni++)
                mma8(acc[mi][ni], af[mi], bf[ni]);
    }
}

// ---------------- K0: pre-round / weight reorder -----------------------------
__global__ void k_round(const float* __restrict__ s, float* __restrict__ d, int n) {
    int i = blockIdx.x * 256 + threadIdx.x;
    if (i < n) d[i] = tf32r(s[i]);
}

// w[co][ci][r3] (OIHW flat) -> d[co][r3*256 + ci], tf32-rounded
__global__ void k_wtrans(const float* __restrict__ w, float* __restrict__ d) {
    int i = blockIdx.x * 256 + threadIdx.x;
    if (i < CC * 2304) {
        int co  = i / 2304;
        int rem = i - co * 2304;
        int r3  = rem >> 8;
        int ci  = rem & 255;
        d[i] = tf32r(w[co * 2304 + ci * 9 + r3]);
    }
}

// ---------------- K1: 1x1 convs -> top/center tf32 hi+lo [B][HW][P] ----------
__global__ void k_top_center(const float* __restrict__ x,
                             const float* __restrict__ wt, const float* __restrict__ bt,
                             const float* __restrict__ wc, const float* __restrict__ bc)
{
    const int b  = blockIdx.y;
    const int n0 = blockIdx.x * 64;
    const int t  = threadIdx.x;
    const int p  = t & 63;
    const int q  = t >> 6;

    __shared__ float xs[16][64];
    __shared__ float wts[64][17];
    __shared__ float wcs[64][17];

    float acct[16], accc[16];
#pragma unroll
    for (int j = 0; j < 16; j++) { acct[j] = 0.f; accc[j] = 0.f; }

    const float* xb = x + (size_t)b * CC * HWS;

    for (int c0 = 0; c0 < CC; c0 += 16) {
        {
            int cc = t >> 4;
            int nn = (t & 15) * 4;
            float4 v = *(const float4*)(xb + (size_t)(c0 + cc) * HWS + n0 + nn);
            *(float4*)&xs[cc][nn] = v;
        }
        {
            int p_ = t >> 2;
            int cq = (t & 3) * 4;
            float4 v = *(const float4*)(wt + (size_t)p_ * CC + c0 + cq);
            wts[p_][cq + 0] = v.x; wts[p_][cq + 1] = v.y; wts[p_][cq + 2] = v.z; wts[p_][cq + 3] = v.w;
            float4 u = *(const float4*)(wc + (size_t)p_ * CC + c0 + cq);
            wcs[p_][cq + 0] = u.x; wcs[p_][cq + 1] = u.y; wcs[p_][cq + 2] = u.z; wcs[p_][cq + 3] = u.w;
        }
        __syncthreads();
#pragma unroll
        for (int cc = 0; cc < 16; cc++) {
            float at = wts[p][cc];
            float ac = wcs[p][cc];
#pragma unroll
            for (int j = 0; j < 16; j++) {
                float xv = xs[cc][q * 16 + j];
                acct[j] += at * xv;
                accc[j] += ac * xv;
            }
        }
        __syncthreads();
    }

    const float btv = bt[p];
    const float bcv = bc[p];
    size_t base = (size_t)b * HWS * PP + (size_t)(n0 + q * 16) * PP + p;
#pragma unroll
    for (int j = 0; j < 16; j++) {
        float vt = acct[j] + btv;
        float vc = accc[j] + bcv;
        float th = tf32r(vt), tl = tf32r(vt - th);
        float ch = tf32r(vc), cl = tf32r(vc - ch);
        size_t o = base + (size_t)j * PP;
        g_topH[o] = th; g_topL[o] = tl;
        g_cenH[o] = ch; g_cenL[o] = cl;
    }
}

// ---------------- conv 3x3: tf32 implicit GEMM, full cp.async pipeline -------
// K order = [r3][ci]: each 32-wide panel has constant (dh,dw) -> coalesced,
// cp.async-able B gather with one OOB check per thread per panel.
template<bool ADDZ>
__global__ void __launch_bounds__(256, 2)
k_conv_t(const float* __restrict__ bias, float* __restrict__ outp)
{
    extern __shared__ float sm[];   // 2 stages x (A 4096 + B 4096 floats) = 64KB
    const uint32_t smb = s2u(sm);

    const int b   = blockIdx.z;
    const int n0  = blockIdx.x * 128;
    const int m0  = blockIdx.y * 128;
    const int tid = threadIdx.x;
    const int wid = tid >> 5, lane = tid & 31;
    const int warp_m = (wid & 1) * 64;
    const int warp_n = (wid >> 1) * 32;

    const int r  = tid >> 1;
    const int kq = (tid & 1) * 4;
    const int n  = n0 + r;
    const int h  = n >> 6, w = n & 63;

    const float* srcB = (ADDZ ? g_xz : g_xr) + (size_t)b * CC * HWS;
    const float* arow = (ADDZ ? g_wor : g_wbr) + (size_t)(m0 + r) * 2304;

    float acc[4][4][4];
#pragma unroll
    for (int mi = 0; mi < 4; mi++)
#pragma unroll
        for (int ni = 0; ni < 4; ni++)
#pragma unroll
            for (int e = 0; e < 4; e++) acc[mi][ni][e] = 0.f;

    auto issue_stage = [&](int c, int bf) {
        uint32_t ab = smb + bf * 32768;
        uint32_t bb = ab + 16384;
        const float* ar = arow + c * 32;
#pragma unroll
        for (int j = 0; j < 4; j++) {
            uint32_t off = 4u * (uint32_t)(r * 32 + (((kq + j) ^ (r & 7)) << 2));
            cpa16(ab + off, ar + (kq + j) * 4);
        }
        int k0 = c * 32;
        int r3 = k0 >> 8;
        int ci0 = k0 & 255;
        int dh = r3 / 3 - 1;
        int dw = r3 - (r3 / 3) * 3 - 1;
        int hh = h + dh, ww = w + dw;
        if ((unsigned)hh < 64u && (unsigned)ww < 64u) {
            const float* sb = srcB + (size_t)ci0 * HWS + hh * 64 + ww;
#pragma unroll
            for (int j = 0; j < 4; j++) {
                int kk = (kq + j) * 4;
                uint32_t off = 4u * (uint32_t)(r * 32 + (((kq + j) ^ (r & 7)) << 2));
                cpa4(bb + off,      sb + (size_t)(kk + 0) * HWS);
                cpa4(bb + off + 4,  sb + (size_t)(kk + 1) * HWS);
                cpa4(bb + off + 8,  sb + (size_t)(kk + 2) * HWS);
                cpa4(bb + off + 12, sb + (size_t)(kk + 3) * HWS);
            }
        } else {
            float* bz = sm + bf * 8192 + 4096;
#pragma unroll
            for (int j = 0; j < 4; j++) {
                int off = r * 32 + (((kq + j) ^ (r & 7)) << 2);
                *(float4*)&bz[off] = make_float4(0.f, 0.f, 0.f, 0.f);
            }
        }
    };

    issue_stage(0, 0);
    CP_COMMIT();

    for (int c = 0; c < 72; c++) {
        int cur = c & 1;
        if (c < 71) {
            issue_stage(c + 1, cur ^ 1);
            CP_COMMIT();
            CP_WAIT(1);
        } else {
            CP_WAIT(0);
        }
        __syncthreads();
        panel_mma(acc, sm + cur * 8192, sm + cur * 8192 + 4096, warp_m, warp_n, lane);
        __syncthreads();
    }

    const int g = lane >> 2, t = lane & 3;
    float* obase = ADDZ ? outp + (size_t)b * CC * HWS
                        : g_bottomT + (size_t)b * CC * HWS;

#pragma unroll
    for (int mi = 0; mi < 4; mi++) {
        int m1 = m0 + warp_m + mi * 16 + g;
        int m2 = m1 + 8;
        float bv1 = bias[m1], bv2 = bias[m2];
#pragma unroll
        for (int ni = 0; ni < 4; ni++) {
            int nn = n0 + warp_n + ni * 8 + 2 * t;
            if (ADDZ) {
                *(float2*)(obase + (size_t)m1 * HWS + nn) =
                    make_float2(acc[mi][ni][0] + bv1, acc[mi][ni][1] + bv1);
                *(float2*)(obase + (size_t)m2 * HWS + nn) =
                    make_float2(acc[mi][ni][2] + bv2, acc[mi][ni][3] + bv2);
            } else {
                *(float2*)(obase + (size_t)m1 * HWS + nn) =
                    make_float2(tf32r(acc[mi][ni][0] + bv1), tf32r(acc[mi][ni][1] + bv1));
                *(float2*)(obase + (size_t)m2 * HWS + nn) =
                    make_float2(tf32r(acc[mi][ni][2] + bv2), tf32r(acc[mi][ni][3] + bv2));
            }
        }
    }
}

// ---------------- S = cen @ top^T (tf32 hi/lo x3) + fused exp/sum ------------
__global__ void __launch_bounds__(256, 1) k_S_t()
{
    extern __shared__ float dyn[];
    float* Ah = dyn;
    float* Al = dyn + 4096;
    float* Bh = dyn + 8192;
    float* Bl = dyn + 12288;
    __shared__ float red[256];

    const int b   = blockIdx.z;
    const int n0  = blockIdx.x * 128;
    const int m0  = blockIdx.y * 128;
    const int tid = threadIdx.x;
    const int wid = tid >> 5, lane = tid & 31;
    const int warp_m = (wid & 1) * 64;
    const int warp_n = (wid >> 1) * 32;
    const int g = lane >> 2, t = lane & 3;

    const int r  = tid >> 1;
    const int kq = (tid & 1) * 4;
    const size_t rowA = ((size_t)b * HWS + m0 + r) * PP;
    const size_t rowB = ((size_t)b * HWS + n0 + r) * PP;

    float acc[4][4][4];
#pragma unroll
    for (int mi = 0; mi < 4; mi++)
#pragma unroll
        for (int ni = 0; ni < 4; ni++)
#pragma unroll
            for (int e = 0; e < 4; e++) acc[mi][ni][e] = 0.f;

    const uint32_t* Ahu = (const uint32_t*)Ah;
    const uint32_t* Alu = (const uint32_t*)Al;
    const uint32_t* Bhu = (const uint32_t*)Bh;
    const uint32_t* Blu = (const uint32_t*)Bl;

    for (int c = 0; c < 2; c++) {
        __syncthreads();
        {
            const float4* pAh = (const float4*)(g_cenH + rowA);
            const float4* pAl = (const float4*)(g_cenL + rowA);
            const float4* pBh = (const float4*)(g_topH + rowB);
            const float4* pBl = (const float4*)(g_topL + rowB);
#pragma unroll
            for (int j = 0; j < 4; j++) {
                int sc = c * 8 + kq + j;
                int d  = r * 32 + (((kq + j) ^ (r & 7)) << 2);
                *(float4*)&Ah[d] = pAh[sc];
                *(float4*)&Al[d] = pAl[sc];
                *(float4*)&Bh[d] = pBh[sc];
                *(float4*)&Bl[d] = pBl[sc];
            }
        }
        __syncthreads();
#pragma unroll
        for (int ks = 0; ks < 4; ks++) {
            int k = ks * 8;
            uint32_t ah[4][4], al[4][4], bh[4][2], bl[4][2];
#pragma unroll
            for (int mi = 0; mi < 4; mi++) {
                int mb = warp_m + mi * 16;
                ah[mi][0] = Ahu[swidx(mb + g,     k + t)];
                ah[mi][1] = Ahu[swidx(mb + g + 8, k + t)];
                ah[mi][2] = Ahu[swidx(mb + g,     k + t + 4)];
                ah[mi][3] = Ahu[swidx(mb + g + 8, k + t + 4)];
                al[mi][0] = Alu[swidx(mb + g,     k + t)];
                al[mi][1] = Alu[swidx(mb + g + 8, k + t)];
                al[mi][2] = Alu[swidx(mb + g,     k + t + 4)];
                al[mi][3] = Alu[swidx(mb + g + 8, k + t + 4)];
            }
#pragma unroll
            for (int ni = 0; ni < 4; ni++) {
                int nb = warp_n + ni * 8;
                bh[ni][0] = Bhu[swidx(nb + g, k + t)];
                bh[ni][1] = Bhu[swidx(nb + g, k + t + 4)];
                bl[ni][0] = Blu[swidx(nb + g, k + t)];
                bl[ni][1] = Blu[swidx(nb + g, k + t + 4)];
            }
#pragma unroll
            for (int mi = 0; mi < 4; mi++)
#pragma unroll
                for (int ni = 0; ni < 4; ni++) {
                    mma8(acc[mi][ni], ah[mi], bh[ni]);
                    mma8(acc[mi][ni], ah[mi], bl[ni]);
                    mma8(acc[mi][ni], al[mi], bh[ni]);
                }
        }
    }

    // epilogue: E = tf32r(exp(S - 40)); sum the ROUNDED values
    float* Eb = g_S + (size_t)b * HWS * HWS;
    float ls = 0.f;
#pragma unroll
    for (int mi = 0; mi < 4; mi++) {
        int m1 = m0 + warp_m + mi * 16 + g;
        int m2 = m1 + 8;
#pragma unroll
        for (int ni = 0; ni < 4; ni++) {
            int nn = n0 + warp_n + ni * 8 + 2 * t;
            float e0 = tf32r(__expf(acc[mi][ni][0] - 40.f));
            float e1 = tf32r(__expf(acc[mi][ni][1] - 40.f));
            float e2 = tf32r(__expf(acc[mi][ni][2] - 40.f));
            float e3 = tf32r(__expf(acc[mi][ni][3] - 40.f));
            ls += (e0 + e1) + (e2 + e3);
            *(float2*)(Eb + (size_t)m1 * HWS + nn) = make_float2(e0, e1);
            *(float2*)(Eb + (size_t)m2 * HWS + nn) = make_float2(e2, e3);
        }
    }
    red[tid] = ls;
    __syncthreads();
    for (int st = 128; st > 0; st >>= 1) {
        if (tid < st) red[tid] += red[tid + st];
        __syncthreads();
    }
    if (tid == 0) g_partialS[b * 1024 + blockIdx.y * 32 + blockIdx.x] = red[0];
}

// ---------------- reduce partial sums ----------------------------------------
__global__ void k_sumreduce()
{
    const int b = blockIdx.x;
    const int tid = threadIdx.x;
    __shared__ float red[256];
    float s = 0.f;
    for (int i = tid; i < 1024; i += 256) s += g_partialS[b * 1024 + i];
    red[tid] = s;
    __syncthreads();
    for (int st = 128; st > 0; st >>= 1) {
        if (tid < st) red[tid] += red[tid + st];
        __syncthreads();
    }
    if (tid == 0) g_sum[b] = red[0];
}

// ---------------- attn: (E/sum)@bottomT^T, cp.async 2-stage; writes x+attn ---
__global__ void __launch_bounds__(256, 2) k_attn_cp(const float* __restrict__ x)
{
    extern __shared__ float sm[];   // 2 x (A 4096 + B 4096) floats = 64KB
    const uint32_t smb = s2u(sm);

    const int b   = blockIdx.z;
    const int cb  = blockIdx.x * 128;   // C tile
    const int m0  = blockIdx.y * 128;   // HW tile
    const int tid = threadIdx.x;
    const int wid = tid >> 5, lane = tid & 31;
    const int warp_m = (wid & 1) * 64;
    const int warp_n = (wid >> 1) * 32;

    const float* A  = g_S       + (size_t)b * HWS * HWS + (size_t)m0 * HWS;
    const float* Bt = g_bottomT + (size_t)b * CC * HWS + (size_t)cb * HWS;

    float acc[4][4][4];
#pragma unroll
    for (int mi = 0; mi < 4; mi++)
#pragma unroll
        for (int ni = 0; ni < 4; ni++)
#pragma unroll
            for (int e = 0; e < 4; e++) acc[mi][ni][e] = 0.f;

    issue_pair(smb, smb + 16384, A, Bt, 0);
    CP_COMMIT();

    for (int c = 0; c < 128; c++) {
        int cur = c & 1;
        if (c < 127) {
            uint32_t nb = smb + (cur ^ 1) * 32768;
            issue_pair(nb, nb + 16384, A, Bt, (c + 1) * 32);
            CP_COMMIT();
            CP_WAIT(1);
        } else {
            CP_WAIT(0);
        }
        __syncthreads();
        panel_mma(acc, sm + cur * 8192, sm + cur * 8192 + 4096, warp_m, warp_n, lane);
        __syncthreads();
    }

    const int g = lane >> 2, t = lane & 3;
    const float inv = 1.0f / g_sum[b];
    const float* xb = x + (size_t)b * CC * HWS;
    float* zb = g_xz + (size_t)b * CC * HWS;

#pragma unroll
    for (int mi = 0; mi < 4; mi++) {
        int m1 = m0 + warp_m + mi * 16 + g;
        int m2 = m1 + 8;
#pragma unroll
        for (int ni = 0; ni < 4; ni++) {
            int nn = cb + warp_n + ni * 8 + 2 * t;
            int f1 = m1 * CC + nn;
            int f2 = m2 * CC + nn;
            float2 x1 = *(const float2*)(xb + f1);
            float2 x2 = *(const float2*)(xb + f2);
            *(float2*)(zb + f1) = make_float2(tf32r(x1.x + acc[mi][ni][0] * inv),
                                              tf32r(x1.y + acc[mi][ni][1] * inv));
            *(float2*)(zb + f2) = make_float2(tf32r(x2.x + acc[mi][ni][2] * inv),
                                              tf32r(x2.y + acc[mi][ni][3] * inv));
        }
    }
}

// ---------------- launch -----------------------------------------------------
extern "C" void kernel_launch(void* const* d_in, const int* in_sizes, int n_in,
                              void* d_out, int out_size)
{
    const float* x   = (const float*)d_in[0];
    const float* wt  = (const float*)d_in[1];
    const float* bt  = (const float*)d_in[2];
    const float* wc  = (const float*)d_in[3];
    const float* bc  = (const float*)d_in[4];
    const float* wb  = (const float*)d_in[5];
    const float* bbm = (const float*)d_in[6];
    const float* wo  = (const float*)d_in[7];
    const float* bo  = (const float*)d_in[8];
    float* out = (float*)d_out;

    cudaFuncSetAttribute(k_conv_t<false>, cudaFuncAttributeMaxDynamicSharedMemorySize, 65536);
    cudaFuncSetAttribute(k_conv_t<true>,  cudaFuncAttributeMaxDynamicSharedMemorySize, 65536);
    cudaFuncSetAttribute(k_S_t,           cudaFuncAttributeMaxDynamicSharedMemorySize, 65536);
    cudaFuncSetAttribute(k_attn_cp,       cudaFuncAttributeMaxDynamicSharedMemorySize, 65536);

    float* d_xr;  cudaGetSymbolAddress((void**)&d_xr,  g_xr);
    float* d_wbr; cudaGetSymbolAddress((void**)&d_wbr, g_wbr);
    float* d_wor; cudaGetSymbolAddress((void**)&d_wor, g_wor);

    k_round<<<(BB * CC * HWS + 255) / 256, 256>>>(x, d_xr, BB * CC * HWS);
    k_wtrans<<<(CC * 2304 + 255) / 256, 256>>>(wb, d_wbr);
    k_wtrans<<<(CC * 2304 + 255) / 256, 256>>>(wo, d_wor);

    k_top_center<<<dim3(HWS / 64, BB), 256>>>(x, wt, bt, wc, bc);
    k_conv_t<false><<<dim3(32, 2, BB), 256, 65536>>>(bbm, nullptr);
    k_S_t<<<dim3(32, 32, BB), 256, 65536>>>();
    k_sumreduce<<<BB, 256>>>();
    k_attn_cp<<<dim3(2, 32, BB), 256, 65536>>>(x);
    k_conv_t<true><<<dim3(32, 2, BB), 256, 65536>>>(bo, out);
}

// round 12
// speedup vs baseline: 2.0731x; 1.6626x over previous
#include <cuda_runtime.h>
#include <cuda_fp16.h>
#include <cuda_bf16.h>
#include <cstdint>

#define BB  8
#define CC  256
#define PP  64
#define HWS 4096
#define HWS2 2048           // u32 (half2/bf162) per row of HWS 16-bit elems

// ---------------- scratch (device globals) -----------------------------------
__device__ __align__(128) __half g_xh  [BB * CC * HWS];   // x, channel-pair interleaved fp16
__device__ __align__(128) __half g_xzh [BB * CC * HWS];   // x + attn, pair interleaved fp16
__device__ __align__(128) __half g_wbh [CC * 2304];       // w_bottom [co][r3*256+ci] fp16
__device__ __align__(128) __half g_woh [CC * 2304];       // w_out    [co][r3*256+ci] fp16
__device__ __align__(128) __half g_topHh[BB * HWS * PP];  // hi ([B][HW][P]) fp16
__device__ __align__(128) __half g_topLh[BB * HWS * PP];  // lo
__device__ __align__(128) __half g_cenHh[BB * HWS * PP];
__device__ __align__(128) __half g_cenLh[BB * HWS * PP];
__device__ __align__(128) __nv_bfloat16 g_botB[BB * CC * HWS];        // bottomT [B][C][HW] bf16
__device__ __align__(128) __nv_bfloat16 g_Eb[(size_t)BB * HWS * HWS]; // E = exp(S-40) bf16, 268MB
__device__ float g_partialS[BB * 1024];
__device__ float g_sum[BB];

// ---------------- helpers ----------------------------------------------------
__device__ __forceinline__ void mma16(float* d, const uint32_t* a, const uint32_t* b) {
    asm volatile(
        "mma.sync.aligned.m16n8k16.row.col.f32.f16.f16.f32 "
        "{%0,%1,%2,%3}, {%4,%5,%6,%7}, {%8,%9}, {%0,%1,%2,%3};"
        : "+f"(d[0]), "+f"(d[1]), "+f"(d[2]), "+f"(d[3])
        : "r"(a[0]), "r"(a[1]), "r"(a[2]), "r"(a[3]), "r"(b[0]), "r"(b[1]));
}
__device__ __forceinline__ void mma16bf(float* d, const uint32_t* a, const uint32_t* b) {
    asm volatile(
        "mma.sync.aligned.m16n8k16.row.col.f32.bf16.bf16.f32 "
        "{%0,%1,%2,%3}, {%4,%5,%6,%7}, {%8,%9}, {%0,%1,%2,%3};"
        : "+f"(d[0]), "+f"(d[1]), "+f"(d[2]), "+f"(d[3])
        : "r"(a[0]), "r"(a[1]), "r"(a[2]), "r"(a[3]), "r"(b[0]), "r"(b[1]));
}

// swizzles: panels are [128 rows] x [16 u32] (64B rows) or [32 u32] (128B rows)
__device__ __forceinline__ int sw16(int r, int c) {
    return r * 16 + ((((c >> 2) ^ ((r >> 1) & 3)) << 2)) + (c & 3);
}
__device__ __forceinline__ int sw32(int r, int c) {
    return r * 32 + ((((c >> 2) ^ (r & 7)) << 2)) + (c & 3);
}

__device__ __forceinline__ uint32_t s2u(const void* p) {
    uint32_t a;
    asm("{ .reg .u64 t; cvta.to.shared.u64 t, %1; cvt.u32.u64 %0, t; }" : "=r"(a) : "l"(p));
    return a;
}
__device__ __forceinline__ void cpa16(uint32_t dst, const void* src) {
    asm volatile("cp.async.cg.shared.global [%0], [%1], 16;" :: "r"(dst), "l"(src));
}
__device__ __forceinline__ void cpa4(uint32_t dst, const void* src) {
    asm volatile("cp.async.ca.shared.global [%0], [%1], 4;" :: "r"(dst), "l"(src));
}
#define CP_COMMIT() asm volatile("cp.async.commit_group;" ::: "memory")
#define CP_WAIT(N)  asm volatile("cp.async.wait_group %0;" :: "n"(N) : "memory")

// ---------------- warp compute: one k32 16-bit panel (64B rows, 2 ksteps) ----
template<bool BF>
__device__ __forceinline__ void panel_mma16(float acc[4][4][4],
                                            const uint32_t* Au, const uint32_t* Bu,
                                            int warp_m, int warp_n, int lane) {
    int g = lane >> 2, t = lane & 3;
#pragma unroll
    for (int ks = 0; ks < 2; ks++) {
        int kb = ks * 8;
        uint32_t af[4][4], bf[4][2];
#pragma unroll
        for (int mi = 0; mi < 4; mi++) {
            int mb = warp_m + mi * 16;
            af[mi][0] = Au[sw16(mb + g,     kb + t)];
            af[mi][1] = Au[sw16(mb + g + 8, kb + t)];
            af[mi][2] = Au[sw16(mb + g,     kb + t + 4)];
            af[mi][3] = Au[sw16(mb + g + 8, kb + t + 4)];
        }
#pragma unroll
        for (int ni = 0; ni < 4; ni++) {
            int nb = warp_n + ni * 8;
            bf[ni][0] = Bu[sw16(nb + g, kb + t)];
            bf[ni][1] = Bu[sw16(nb + g, kb + t + 4)];
        }
#pragma unroll
        for (int mi = 0; mi < 4; mi++)
#pragma unroll
            for (int ni = 0; ni < 4; ni++) {
                if (BF) mma16bf(acc[mi][ni], af[mi], bf[ni]);
                else    mma16  (acc[mi][ni], af[mi], bf[ni]);
            }
    }
}

// ---------------- K0a: pack x -> fp16 channel-pair-interleaved ---------------
__global__ void k_xpack(const float* __restrict__ x) {
    int i = blockIdx.x * 256 + threadIdx.x;          // over BB*128*HWS
    if (i < BB * 128 * HWS) {
        int b   = i / (128 * HWS);
        int rem = i - b * 128 * HWS;
        int cp  = rem >> 12;
        int hw  = rem & 4095;
        const float* src = x + ((size_t)(b * CC + 2 * cp) * HWS + hw);
        __half2 v = __floats2half2_rn(src[0], src[HWS]);
        ((__half2*)g_xh)[i] = v;
    }
}

// ---------------- K0b: weight reorder+fp16: [co][ci][r3] -> [co][r3*256+ci] --
__global__ void k_wtransH(const float* __restrict__ w, __half* __restrict__ d) {
    int i = blockIdx.x * 256 + threadIdx.x;
    if (i < CC * 2304) {
        int co  = i / 2304;
        int rem = i - co * 2304;
        int r3  = rem >> 8;
        int ci  = rem & 255;
        d[i] = __float2half_rn(w[co * 2304 + ci * 9 + r3]);
    }
}

// ---------------- K1: 1x1 convs -> top/center fp16 hi+lo [B][HW][P] ----------
__global__ void k_top_center(const float* __restrict__ x,
                             const float* __restrict__ wt, const float* __restrict__ bt,
                             const float* __restrict__ wc, const float* __restrict__ bc)
{
    const int b  = blockIdx.y;
    const int n0 = blockIdx.x * 64;
    const int t  = threadIdx.x;
    const int p  = t & 63;
    const int q  = t >> 6;

    __shared__ float xs[16][64];
    __shared__ float wts[64][17];
    __shared__ float wcs[64][17];

    float acct[16], accc[16];
#pragma unroll
    for (int j = 0; j < 16; j++) { acct[j] = 0.f; accc[j] = 0.f; }

    const float* xb = x + (size_t)b * CC * HWS;

    for (int c0 = 0; c0 < CC; c0 += 16) {
        {
            int cc = t >> 4;
            int nn = (t & 15) * 4;
            float4 v = *(const float4*)(xb + (size_t)(c0 + cc) * HWS + n0 + nn);
            *(float4*)&xs[cc][nn] = v;
        }
        {
            int p_ = t >> 2;
            int cq = (t & 3) * 4;
            float4 v = *(const float4*)(wt + (size_t)p_ * CC + c0 + cq);
            wts[p_][cq + 0] = v.x; wts[p_][cq + 1] = v.y; wts[p_][cq + 2] = v.z; wts[p_][cq + 3] = v.w;
            float4 u = *(const float4*)(wc + (size_t)p_ * CC + c0 + cq);
            wcs[p_][cq + 0] = u.x; wcs[p_][cq + 1] = u.y; wcs[p_][cq + 2] = u.z; wcs[p_][cq + 3] = u.w;
        }
        __syncthreads();
#pragma unroll
        for (int cc = 0; cc < 16; cc++) {
            float at = wts[p][cc];
            float ac = wcs[p][cc];
#pragma unroll
            for (int j = 0; j < 16; j++) {
                float xv = xs[cc][q * 16 + j];
                acct[j] += at * xv;
                accc[j] += ac * xv;
            }
        }
        __syncthreads();
    }

    const float btv = bt[p];
    const float bcv = bc[p];
    size_t base = (size_t)b * HWS * PP + (size_t)(n0 + q * 16) * PP + p;
#pragma unroll
    for (int j = 0; j < 16; j++) {
        float vt = acct[j] + btv;
        float vc = accc[j] + bcv;
        __half th = __float2half_rn(vt);
        __half tl = __float2half_rn(vt - __half2float(th));
        __half ch = __float2half_rn(vc);
        __half cl = __float2half_rn(vc - __half2float(ch));
        size_t o = base + (size_t)j * PP;
        g_topHh[o] = th; g_topLh[o] = tl;
        g_cenHh[o] = ch; g_cenLh[o] = cl;
    }
}

// ---------------- conv 3x3: fp16 implicit GEMM, 4-stage cp.async ring --------
// K order [r3][ci]; B source = pair-interleaved fp16 image.
template<bool ADDZ>
__global__ void __launch_bounds__(256, 2)
k_conv_h(const float* __restrict__ bias, float* __restrict__ outp)
{
    extern __shared__ uint32_t sm[];   // 4 stages x (A 2048 + B 2048 u32) = 64KB
    const uint32_t smb = s2u(sm);

    const int b   = blockIdx.z;
    const int n0  = blockIdx.x * 128;
    const int m0  = blockIdx.y * 128;
    const int tid = threadIdx.x;
    const int wid = tid >> 5, lane = tid & 31;
    const int warp_m = (wid & 1) * 64;
    const int warp_n = (wid >> 1) * 32;

    const int r  = tid >> 1;
    const int hf = tid & 1;
    const int n  = n0 + r;
    const int h  = n >> 6, w = n & 63;

    const uint32_t* xbase = (const uint32_t*)(ADDZ ? g_xzh : g_xh) + (size_t)b * 128 * HWS;
    const uint32_t* arow  = (const uint32_t*)(ADDZ ? g_woh : g_wbh) + (size_t)(m0 + r) * 1152;

    float acc[4][4][4];
#pragma unroll
    for (int mi = 0; mi < 4; mi++)
#pragma unroll
        for (int ni = 0; ni < 4; ni++)
#pragma unroll
            for (int e = 0; e < 4; e++) acc[mi][ni][e] = 0.f;

    auto issue_stage = [&](int c, int st) {
        uint32_t ab = smb + st * 16384;
        uint32_t bb = ab + 8192;
        int k0 = c * 32;
        const uint32_t* ar = arow + (k0 >> 1);
#pragma unroll
        for (int j = 0; j < 2; j++) {
            int cq = hf * 2 + j;
            cpa16(ab + 4u * (uint32_t)(r * 16 + ((cq ^ ((r >> 1) & 3)) << 2)), ar + cq * 4);
        }
        int r3  = k0 >> 8;
        int cp0 = (k0 & 255) >> 1;
        int dh  = r3 / 3 - 1;
        int dw  = r3 - (r3 / 3) * 3 - 1;
        int hh = h + dh, ww = w + dw;
        if ((unsigned)hh < 64u && (unsigned)ww < 64u) {
            const uint32_t* src = xbase + (size_t)cp0 * HWS + hh * 64 + ww;
#pragma unroll
            for (int j = 0; j < 8; j++) {
                int c4 = hf * 8 + j;
                uint32_t off = 4u * (uint32_t)sw16(r, c4);
                cpa4(bb + off, src + (size_t)c4 * HWS);
            }
        } else {
            uint32_t* bz = sm + st * 4096 + 2048;
#pragma unroll
            for (int j = 0; j < 2; j++) {
                int cq = hf * 2 + j;
                *(uint4*)&bz[r * 16 + ((cq ^ ((r >> 1) & 3)) << 2)] = make_uint4(0, 0, 0, 0);
            }
        }
    };

    const int NC = 72;
    issue_stage(0, 0); CP_COMMIT();
    issue_stage(1, 1); CP_COMMIT();
    issue_stage(2, 2); CP_COMMIT();

    for (int c = 0; c < NC; c++) {
        CP_WAIT(2);
        __syncthreads();
        int ip = (c + 3 < NC) ? c + 3 : 0;     // dummy re-issue keeps group count exact
        issue_stage(ip, (c + 3) & 3);
        CP_COMMIT();
        int st = c & 3;
        panel_mma16<false>(acc, sm + st * 4096, sm + st * 4096 + 2048, warp_m, warp_n, lane);
    }

    const int g = lane >> 2, t = lane & 3;
#pragma unroll
    for (int mi = 0; mi < 4; mi++) {
        int m1 = m0 + warp_m + mi * 16 + g;
        int m2 = m1 + 8;
        float bv1 = bias[m1], bv2 = bias[m2];
#pragma unroll
        for (int ni = 0; ni < 4; ni++) {
            int nn = n0 + warp_n + ni * 8 + 2 * t;
            if (ADDZ) {
                float* ob = outp + (size_t)b * CC * HWS;
                *(float2*)(ob + (size_t)m1 * HWS + nn) =
                    make_float2(acc[mi][ni][0] + bv1, acc[mi][ni][1] + bv1);
                *(float2*)(ob + (size_t)m2 * HWS + nn) =
                    make_float2(acc[mi][ni][2] + bv2, acc[mi][ni][3] + bv2);
            } else {
                __nv_bfloat162* ob = (__nv_bfloat162*)g_botB + ((size_t)b * CC * HWS >> 1);
                ob[((size_t)m1 * HWS + nn) >> 1] =
                    __floats2bfloat162_rn(acc[mi][ni][0] + bv1, acc[mi][ni][1] + bv1);
                ob[((size_t)m2 * HWS + nn) >> 1] =
                    __floats2bfloat162_rn(acc[mi][ni][2] + bv2, acc[mi][ni][3] + bv2);
            }
        }
    }
}

// ---------------- S = cen @ top^T (fp16 hi/lo x3) + fused exp/sum ------------
__global__ void __launch_bounds__(256, 1) k_S_h()
{
    extern __shared__ uint32_t dynS[];    // Ah,Al,Bh,Bl each [128][32]u32 = 64KB
    uint32_t* Ah = dynS;
    uint32_t* Al = dynS + 4096;
    uint32_t* Bh = dynS + 8192;
    uint32_t* Bl = dynS + 12288;
    __shared__ float red[256];

    const int b   = blockIdx.z;
    const int n0  = blockIdx.x * 128;
    const int m0  = blockIdx.y * 128;
    const int tid = threadIdx.x;
    const int wid = tid >> 5, lane = tid & 31;
    const int warp_m = (wid & 1) * 64;
    const int warp_n = (wid >> 1) * 32;
    const int g = lane >> 2, t = lane & 3;

    // single-shot load: K=64 halves = 32 u32 per row, 4 panels
    {
        int r  = tid >> 1;
        int hf = tid & 1;
        size_t rowA = ((size_t)b * HWS + m0 + r) * 32;   // u32 units (PP/2)
        size_t rowB = ((size_t)b * HWS + n0 + r) * 32;
        const uint4* pAh = (const uint4*)((const uint32_t*)g_cenHh + rowA);
        const uint4* pAl = (const uint4*)((const uint32_t*)g_cenLh + rowA);
        const uint4* pBh = (const uint4*)((const uint32_t*)g_topHh + rowB);
        const uint4* pBl = (const uint4*)((const uint32_t*)g_topLh + rowB);
#pragma unroll
        for (int j = 0; j < 4; j++) {
            int cq = hf * 4 + j;
            int d  = r * 32 + ((cq ^ (r & 7)) << 2);
            *(uint4*)&Ah[d] = pAh[cq];
            *(uint4*)&Al[d] = pAl[cq];
            *(uint4*)&Bh[d] = pBh[cq];
            *(uint4*)&Bl[d] = pBl[cq];
        }
    }
    __syncthreads();

    float acc[4][4][4];
#pragma unroll
    for (int mi = 0; mi < 4; mi++)
#pragma unroll
        for (int ni = 0; ni < 4; ni++)
#pragma unroll
            for (int e = 0; e < 4; e++) acc[mi][ni][e] = 0.f;

#pragma unroll
    for (int ks = 0; ks < 4; ks++) {
        int kb = ks * 8;
        uint32_t ah[4][4], al[4][4], bh[4][2], bl[4][2];
#pragma unroll
        for (int mi = 0; mi < 4; mi++) {
            int mb = warp_m + mi * 16;
            ah[mi][0] = Ah[sw32(mb + g,     kb + t)];
            ah[mi][1] = Ah[sw32(mb + g + 8, kb + t)];
            ah[mi][2] = Ah[sw32(mb + g,     kb + t + 4)];
            ah[mi][3] = Ah[sw32(mb + g + 8, kb + t + 4)];
            al[mi][0] = Al[sw32(mb + g,     kb + t)];
            al[mi][1] = Al[sw32(mb + g + 8, kb + t)];
            al[mi][2] = Al[sw32(mb + g,     kb + t + 4)];
            al[mi][3] = Al[sw32(mb + g + 8, kb + t + 4)];
        }
#pragma unroll
        for (int ni = 0; ni < 4; ni++) {
            int nb = warp_n + ni * 8;
            bh[ni][0] = Bh[sw32(nb + g, kb + t)];
            bh[ni][1] = Bh[sw32(nb + g, kb + t + 4)];
            bl[ni][0] = Bl[sw32(nb + g, kb + t)];
            bl[ni][1] = Bl[sw32(nb + g, kb + t + 4)];
        }
#pragma unroll
        for (int mi = 0; mi < 4; mi++)
#pragma unroll
            for (int ni = 0; ni < 4; ni++) {
                mma16(acc[mi][ni], ah[mi], bh[ni]);
                mma16(acc[mi][ni], ah[mi], bl[ni]);
                mma16(acc[mi][ni], al[mi], bh[ni]);
            }
    }

    // epilogue: E = bf16(exp(S - 40)); deterministic sum of the ROUNDED values
    __nv_bfloat162* Eb = (__nv_bfloat162*)(g_Eb + (size_t)b * HWS * HWS);
    float ls = 0.f;
#pragma unroll
    for (int mi = 0; mi < 4; mi++) {
        int m1 = m0 + warp_m + mi * 16 + g;
        int m2 = m1 + 8;
#pragma unroll
        for (int ni = 0; ni < 4; ni++) {
            int nn = n0 + warp_n + ni * 8 + 2 * t;
            __nv_bfloat16 h0 = __float2bfloat16(__expf(acc[mi][ni][0] - 40.f));
            __nv_bfloat16 h1 = __float2bfloat16(__expf(acc[mi][ni][1] - 40.f));
            __nv_bfloat16 h2 = __float2bfloat16(__expf(acc[mi][ni][2] - 40.f));
            __nv_bfloat16 h3 = __float2bfloat16(__expf(acc[mi][ni][3] - 40.f));
            ls += (__bfloat162float(h0) + __bfloat162float(h1)) +
                  (__bfloat162float(h2) + __bfloat162float(h3));
            Eb[((size_t)m1 * HWS + nn) >> 1] = __nv_bfloat162(h0, h1);
            Eb[((size_t)m2 * HWS + nn) >> 1] = __nv_bfloat162(h2, h3);
        }
    }
    red[tid] = ls;
    __syncthreads();
    for (int st = 128; st > 0; st >>= 1) {
        if (tid < st) red[tid] += red[tid + st];
        __syncthreads();
    }
    if (tid == 0) g_partialS[b * 1024 + blockIdx.y * 32 + blockIdx.x] = red[0];
}

// ---------------- reduce partial sums ----------------------------------------
__global__ void k_sumreduce()
{
    const int b = blockIdx.x;
    const int tid = threadIdx.x;
    __shared__ float red[256];
    float s = 0.f;
    for (int i = tid; i < 1024; i += 256) s += g_partialS[b * 1024 + i];
    red[tid] = s;
    __syncthreads();
    for (int st = 128; st > 0; st >>= 1) {
        if (tid < st) red[tid] += red[tid + st];
        __syncthreads();
    }
    if (tid == 0) g_sum[b] = red[0];
}

// ---------------- attn: (E/sum)@bottomT^T bf16, 4-stage; writes x+attn fp16 --
__global__ void __launch_bounds__(256, 2) k_attn_h(const float* __restrict__ x)
{
    extern __shared__ uint32_t sm[];   // 4 stages x (A 2048 + B 2048 u32) = 64KB
    const uint32_t smb = s2u(sm);

    const int b   = blockIdx.z;
    const int cb  = blockIdx.x * 128;   // C tile
    const int m0  = blockIdx.y * 128;   // HW tile
    const int tid = threadIdx.x;
    const int wid = tid >> 5, lane = tid & 31;
    const int warp_m = (wid & 1) * 64;
    const int warp_n = (wid >> 1) * 32;

    const int r  = tid >> 1;
    const int hf = tid & 1;

    const uint32_t* Arow = (const uint32_t*)g_Eb + ((size_t)b * HWS + m0 + r) * HWS2;
    const uint32_t* Brow = (const uint32_t*)g_botB + ((size_t)b * CC + cb + r) * HWS2;

    float acc[4][4][4];
#pragma unroll
    for (int mi = 0; mi < 4; mi++)
#pragma unroll
        for (int ni = 0; ni < 4; ni++)
#pragma unroll
            for (int e = 0; e < 4; e++) acc[mi][ni][e] = 0.f;

    auto issue_stage = [&](int c, int st) {
        uint32_t ab = smb + st * 16384;
        uint32_t bb = ab + 8192;
        int ku = c * 16;   // u32 offset of this k32 panel
#pragma unroll
        for (int j = 0; j < 2; j++) {
            int cq = hf * 2 + j;
            uint32_t off = 4u * (uint32_t)(r * 16 + ((cq ^ ((r >> 1) & 3)) << 2));
            cpa16(ab + off, Arow + ku + cq * 4);
            cpa16(bb + off, Brow + ku + cq * 4);
        }
    };

    const int NC = 128;
    issue_stage(0, 0); CP_COMMIT();
    issue_stage(1, 1); CP_COMMIT();
    issue_stage(2, 2); CP_COMMIT();

    for (int c = 0; c < NC; c++) {
        CP_WAIT(2);
        __syncthreads();
        int ip = (c + 3 < NC) ? c + 3 : 0;
        issue_stage(ip, (c + 3) & 3);
        CP_COMMIT();
        int st = c & 3;
        panel_mma16<true>(acc, sm + st * 4096, sm + st * 4096 + 2048, warp_m, warp_n, lane);
    }

    const int g = lane >> 2, t = lane & 3;
    const float inv = 1.0f / g_sum[b];
    const float* xb = x + (size_t)b * CC * HWS;
    __half* zb = g_xzh + (size_t)b * CC * HWS;

#pragma unroll
    for (int mi = 0; mi < 4; mi++) {
        int mrows[2] = { m0 + warp_m + mi * 16 + g, m0 + warp_m + mi * 16 + g + 8 };
#pragma unroll
        for (int ni = 0; ni < 4; ni++) {
            int nn = cb + warp_n + ni * 8 + 2 * t;
#pragma unroll
            for (int hrow = 0; hrow < 2; hrow++) {
                int f = mrows[hrow] * CC + nn;
                float2 xv = *(const float2*)(xb + f);
                float v0 = xv.x + acc[mi][ni][hrow * 2 + 0] * inv;
                float v1 = xv.y + acc[mi][ni][hrow * 2 + 1] * inv;
                // pair-interleaved store: element (c,hw) -> half idx ((c>>1)*HWS+hw)*2 + (c&1)
                int c0 = f >> 12,        hw0 = f & 4095;
                int c1 = (f + 1) >> 12,  hw1 = (f + 1) & 4095;
                zb[((size_t)(c0 >> 1) * HWS + hw0) * 2 + (c0 & 1)] = __float2half_rn(v0);
                zb[((size_t)(c1 >> 1) * HWS + hw1) * 2 + (c1 & 1)] = __float2half_rn(v1);
            }
        }
    }
}

// ---------------- launch -----------------------------------------------------
extern "C" void kernel_launch(void* const* d_in, const int* in_sizes, int n_in,
                              void* d_out, int out_size)
{
    const float* x   = (const float*)d_in[0];
    const float* wt  = (const float*)d_in[1];
    const float* bt  = (const float*)d_in[2];
    const float* wc  = (const float*)d_in[3];
    const float* bc  = (const float*)d_in[4];
    const float* wb  = (const float*)d_in[5];
    const float* bbm = (const float*)d_in[6];
    const float* wo  = (const float*)d_in[7];
    const float* bo  = (const float*)d_in[8];
    float* out = (float*)d_out;

    cudaFuncSetAttribute(k_conv_h<false>, cudaFuncAttributeMaxDynamicSharedMemorySize, 65536);
    cudaFuncSetAttribute(k_conv_h<true>,  cudaFuncAttributeMaxDynamicSharedMemorySize, 65536);
    cudaFuncSetAttribute(k_S_h,           cudaFuncAttributeMaxDynamicSharedMemorySize, 65536);
    cudaFuncSetAttribute(k_attn_h,        cudaFuncAttributeMaxDynamicSharedMemorySize, 65536);

    __half* d_wbh; cudaGetSymbolAddress((void**)&d_wbh, g_wbh);
    __half* d_woh; cudaGetSymbolAddress((void**)&d_woh, g_woh);

    k_xpack<<<(BB * 128 * HWS + 255) / 256, 256>>>(x);
    k_wtransH<<<(CC * 2304 + 255) / 256, 256>>>(wb, d_wbh);
    k_wtransH<<<(CC * 2304 + 255) / 256, 256>>>(wo, d_woh);

    k_top_center<<<dim3(HWS / 64, BB), 256>>>(x, wt, bt, wc, bc);
    k_conv_h<false><<<dim3(32, 2, BB), 256, 65536>>>(bbm, nullptr);
    k_S_h<<<dim3(32, 32, BB), 256, 65536>>>();
    k_sumreduce<<<BB, 256>>>();
    k_attn_h<<<dim3(2, 32, BB), 256, 65536>>>(x);
    k_conv_h<true><<<dim3(32, 2, BB), 256, 65536>>>(bo, out);
}

// round 14
// speedup vs baseline: 2.6415x; 1.2741x over previous
#include <cuda_runtime.h>
#include <cuda_fp16.h>
#include <cuda_bf16.h>
#include <cstdint>

#define BB  8
#define CC  256
#define PP  64
#define HWS 4096
#define HWS2 2048           // u32 (half2/bf162) per row of HWS 16-bit elems

// ---------------- scratch (device globals) -----------------------------------
__device__ __align__(128) __half g_xh  [BB * CC * HWS];   // x, channel-pair interleaved fp16
__device__ __align__(128) __half g_xzh [BB * CC * HWS];   // x + attn, pair interleaved fp16
__device__ __align__(128) __half g_wbh [CC * 2304];       // w_bottom [co][r3*256+ci] fp16
__device__ __align__(128) __half g_woh [CC * 2304];       // w_out    [co][r3*256+ci] fp16
__device__ __align__(128) __half g_topHh[BB * HWS * PP];  // hi ([B][HW][P]) fp16
__device__ __align__(128) __half g_topLh[BB * HWS * PP];  // lo
__device__ __align__(128) __half g_cenHh[BB * HWS * PP];
__device__ __align__(128) __half g_cenLh[BB * HWS * PP];
__device__ __align__(128) __nv_bfloat16 g_botB[BB * CC * HWS];        // bottomT [B][C][HW] bf16
__device__ __align__(128) __nv_bfloat16 g_Eb[(size_t)BB * HWS * HWS]; // E = exp(S-40) bf16, 268MB
__device__ float g_partialS[BB * 1024];
__device__ float g_sum[BB];

// ---------------- helpers ----------------------------------------------------
__device__ __forceinline__ void mma16(float* d, const uint32_t* a, const uint32_t* b) {
    asm volatile(
        "mma.sync.aligned.m16n8k16.row.col.f32.f16.f16.f32 "
        "{%0,%1,%2,%3}, {%4,%5,%6,%7}, {%8,%9}, {%0,%1,%2,%3};"
        : "+f"(d[0]), "+f"(d[1]), "+f"(d[2]), "+f"(d[3])
        : "r"(a[0]), "r"(a[1]), "r"(a[2]), "r"(a[3]), "r"(b[0]), "r"(b[1]));
}
__device__ __forceinline__ void mma16bf(float* d, const uint32_t* a, const uint32_t* b) {
    asm volatile(
        "mma.sync.aligned.m16n8k16.row.col.f32.bf16.bf16.f32 "
        "{%0,%1,%2,%3}, {%4,%5,%6,%7}, {%8,%9}, {%0,%1,%2,%3};"
        : "+f"(d[0]), "+f"(d[1]), "+f"(d[2]), "+f"(d[3])
        : "r"(a[0]), "r"(a[1]), "r"(a[2]), "r"(a[3]), "r"(b[0]), "r"(b[1]));
}
#define LDSM4(r0, r1, r2, r3, ad) \
    asm volatile("ldmatrix.sync.aligned.m8n8.x4.shared.b16 {%0,%1,%2,%3}, [%4];" \
        : "=r"(r0), "=r"(r1), "=r"(r2), "=r"(r3) : "r"(ad))

// swizzles: panels are [128 rows] x [16 u32] (64B rows) or [32 u32] (128B rows)
__device__ __forceinline__ int sw16(int r, int c) {
    return r * 16 + ((((c >> 2) ^ ((r >> 1) & 3)) << 2)) + (c & 3);
}
__device__ __forceinline__ int sw32(int r, int c) {
    return r * 32 + ((((c >> 2) ^ (r & 7)) << 2)) + (c & 3);
}

__device__ __forceinline__ uint32_t s2u(const void* p) {
    uint32_t a;
    asm("{ .reg .u64 t; cvta.to.shared.u64 t, %1; cvt.u32.u64 %0, t; }" : "=r"(a) : "l"(p));
    return a;
}
__device__ __forceinline__ void cpa16(uint32_t dst, const void* src) {
    asm volatile("cp.async.cg.shared.global [%0], [%1], 16;" :: "r"(dst), "l"(src));
}
__device__ __forceinline__ void cpa4(uint32_t dst, const void* src) {
    asm volatile("cp.async.ca.shared.global [%0], [%1], 4;" :: "r"(dst), "l"(src));
}
#define CP_COMMIT() asm volatile("cp.async.commit_group;" ::: "memory")
#define CP_WAIT(N)  asm volatile("cp.async.wait_group %0;" :: "n"(N) : "memory")

// ---------------- warp compute: one k32 16-bit panel, ldmatrix loads ---------
template<bool BF>
__device__ __forceinline__ void panel_mma16(float acc[4][4][4],
                                            uint32_t smA, uint32_t smB,
                                            int warp_m, int warp_n, int lane) {
    const int a_row = warp_m + (lane & 15);
    const int a_chk = (lane >> 4) << 2;          // 0 or 4 (u32)
    const int b_row = warp_n + ((lane >> 4) << 3) + (lane & 7);
    const int b_chk = ((lane >> 3) & 1) << 2;    // 0 or 4
#pragma unroll
    for (int ks = 0; ks < 2; ks++) {
        int kb = ks * 8;
        uint32_t af[4][4], bf[4][2];
#pragma unroll
        for (int mi = 0; mi < 4; mi++) {
            uint32_t ad = smA + 4u * (uint32_t)sw16(a_row + mi * 16, kb + a_chk);
            LDSM4(af[mi][0], af[mi][1], af[mi][2], af[mi][3], ad);
        }
#pragma unroll
        for (int np = 0; np < 2; np++) {
            uint32_t bd = smB + 4u * (uint32_t)sw16(b_row + np * 16, kb + b_chk);
            LDSM4(bf[np*2][0], bf[np*2][1], bf[np*2+1][0], bf[np*2+1][1], bd);
        }
#pragma unroll
        for (int mi = 0; mi < 4; mi++)
#pragma unroll
            for (int ni = 0; ni < 4; ni++) {
                if (BF) mma16bf(acc[mi][ni], af[mi], bf[ni]);
                else    mma16  (acc[mi][ni], af[mi], bf[ni]);
            }
    }
}

// ---------------- K0a: pack x -> fp16 channel-pair-interleaved ---------------
__global__ void k_xpack(const float* __restrict__ x) {
    int i = blockIdx.x * 256 + threadIdx.x;          // over BB*128*HWS
    if (i < BB * 128 * HWS) {
        int b   = i / (128 * HWS);
        int rem = i - b * 128 * HWS;
        int cp  = rem >> 12;
        int hw  = rem & 4095;
        const float* src = x + ((size_t)(b * CC + 2 * cp) * HWS + hw);
        __half2 v = __floats2half2_rn(src[0], src[HWS]);
        ((__half2*)g_xh)[i] = v;
    }
}

// ---------------- K0b: weight reorder+fp16: [co][ci][r3] -> [co][r3*256+ci] --
__global__ void k_wtransH(const float* __restrict__ w, __half* __restrict__ d) {
    int i = blockIdx.x * 256 + threadIdx.x;
    if (i < CC * 2304) {
        int co  = i / 2304;
        int rem = i - co * 2304;
        int r3  = rem >> 8;
        int ci  = rem & 255;
        d[i] = __float2half_rn(w[co * 2304 + ci * 9 + r3]);
    }
}

// ---------------- K1: 1x1 convs -> top/center fp16 hi+lo [B][HW][P] ----------
__global__ void k_top_center(const float* __restrict__ x,
                             const float* __restrict__ wt, const float* __restrict__ bt,
                             const float* __restrict__ wc, const float* __restrict__ bc)
{
    const int b  = blockIdx.y;
    const int n0 = blockIdx.x * 64;
    const int t  = threadIdx.x;
    const int p  = t & 63;
    const int q  = t >> 6;

    __shared__ float xs[16][64];
    __shared__ float wts[64][17];
    __shared__ float wcs[64][17];

    float acct[16], accc[16];
#pragma unroll
    for (int j = 0; j < 16; j++) { acct[j] = 0.f; accc[j] = 0.f; }

    const float* xb = x + (size_t)b * CC * HWS;

    for (int c0 = 0; c0 < CC; c0 += 16) {
        {
            int cc = t >> 4;
            int nn = (t & 15) * 4;
            float4 v = *(const float4*)(xb + (size_t)(c0 + cc) * HWS + n0 + nn);
            *(float4*)&xs[cc][nn] = v;
        }
        {
            int p_ = t >> 2;
            int cq = (t & 3) * 4;
            float4 v = *(const float4*)(wt + (size_t)p_ * CC + c0 + cq);
            wts[p_][cq + 0] = v.x; wts[p_][cq + 1] = v.y; wts[p_][cq + 2] = v.z; wts[p_][cq + 3] = v.w;
            float4 u = *(const float4*)(wc + (size_t)p_ * CC + c0 + cq);
            wcs[p_][cq + 0] = u.x; wcs[p_][cq + 1] = u.y; wcs[p_][cq + 2] = u.z; wcs[p_][cq + 3] = u.w;
        }
        __syncthreads();
#pragma unroll
        for (int cc = 0; cc < 16; cc++) {
            float at = wts[p][cc];
            float ac = wcs[p][cc];
#pragma unroll
            for (int j = 0; j < 16; j++) {
                float xv = xs[cc][q * 16 + j];
                acct[j] += at * xv;
                accc[j] += ac * xv;
            }
        }
        __syncthreads();
    }

    const float btv = bt[p];
    const float bcv = bc[p];
    size_t base = (size_t)b * HWS * PP + (size_t)(n0 + q * 16) * PP + p;
#pragma unroll
    for (int j = 0; j < 16; j++) {
        float vt = acct[j] + btv;
        float vc = accc[j] + bcv;
        __half th = __float2half_rn(vt);
        __half tl = __float2half_rn(vt - __half2float(th));
        __half ch = __float2half_rn(vc);
        __half cl = __float2half_rn(vc - __half2float(ch));
        size_t o = base + (size_t)j * PP;
        g_topHh[o] = th; g_topLh[o] = tl;
        g_cenHh[o] = ch; g_cenLh[o] = cl;
    }
}

// ---------------- conv 3x3: fp16 implicit GEMM, 4-stage cp.async ring --------
// K order [r3][ci]; B source = pair-interleaved fp16 image.
template<bool ADDZ>
__global__ void __launch_bounds__(256, 2)
k_conv_h(const float* __restrict__ bias, float* __restrict__ outp)
{
    extern __shared__ uint32_t sm[];   // 4 stages x (A 2048 + B 2048 u32) = 64KB
    const uint32_t smb = s2u(sm);

    const int b   = blockIdx.z;
    const int n0  = blockIdx.x * 128;
    const int m0  = blockIdx.y * 128;
    const int tid = threadIdx.x;
    const int wid = tid >> 5, lane = tid & 31;
    const int warp_m = (wid & 1) * 64;
    const int warp_n = (wid >> 1) * 32;

    const int r  = tid >> 1;
    const int hf = tid & 1;
    const int n  = n0 + r;
    const int h  = n >> 6, w = n & 63;

    const uint32_t* xbase = (const uint32_t*)(ADDZ ? g_xzh : g_xh) + (size_t)b * 128 * HWS;
    const uint32_t* arow  = (const uint32_t*)(ADDZ ? g_woh : g_wbh) + (size_t)(m0 + r) * 1152;

    float acc[4][4][4];
#pragma unroll
    for (int mi = 0; mi < 4; mi++)
#pragma unroll
        for (int ni = 0; ni < 4; ni++)
#pragma unroll
            for (int e = 0; e < 4; e++) acc[mi][ni][e] = 0.f;

    auto issue_stage = [&](int c, int st) {
        uint32_t ab = smb + st * 16384;
        uint32_t bb = ab + 8192;
        int k0 = c * 32;
        const uint32_t* ar = arow + (k0 >> 1);
#pragma unroll
        for (int j = 0; j < 2; j++) {
            int cq = hf * 2 + j;
            cpa16(ab + 4u * (uint32_t)(r * 16 + ((cq ^ ((r >> 1) & 3)) << 2)), ar + cq * 4);
        }
        int r3  = k0 >> 8;
        int cp0 = (k0 & 255) >> 1;
        int dh  = r3 / 3 - 1;
        int dw  = r3 - (r3 / 3) * 3 - 1;
        int hh = h + dh, ww = w + dw;
        if ((unsigned)hh < 64u && (unsigned)ww < 64u) {
            const uint32_t* src = xbase + (size_t)cp0 * HWS + hh * 64 + ww;
#pragma unroll
            for (int j = 0; j < 8; j++) {
                int c4 = hf * 8 + j;
                uint32_t off = 4u * (uint32_t)sw16(r, c4);
                cpa4(bb + off, src + (size_t)c4 * HWS);
            }
        } else {
            uint32_t* bz = sm + st * 4096 + 2048;
#pragma unroll
            for (int j = 0; j < 2; j++) {
                int cq = hf * 2 + j;
                *(uint4*)&bz[r * 16 + ((cq ^ ((r >> 1) & 3)) << 2)] = make_uint4(0, 0, 0, 0);
            }
        }
    };

    const int NC = 72;
    issue_stage(0, 0); CP_COMMIT();
    issue_stage(1, 1); CP_COMMIT();
    issue_stage(2, 2); CP_COMMIT();

    for (int c = 0; c < NC; c++) {
        CP_WAIT(2);
        __syncthreads();
        int ip = (c + 3 < NC) ? c + 3 : 0;     // dummy re-issue keeps group count exact
        issue_stage(ip, (c + 3) & 3);
        CP_COMMIT();
        int st = c & 3;
        panel_mma16<false>(acc, smb + st * 16384, smb + st * 16384 + 8192, warp_m, warp_n, lane);
    }

    const int g = lane >> 2, t = lane & 3;
#pragma unroll
    for (int mi = 0; mi < 4; mi++) {
        int m1 = m0 + warp_m + mi * 16 + g;
        int m2 = m1 + 8;
        float bv1 = bias[m1], bv2 = bias[m2];
#pragma unroll
        for (int ni = 0; ni < 4; ni++) {
            int nn = n0 + warp_n + ni * 8 + 2 * t;
            if (ADDZ) {
                float* ob = outp + (size_t)b * CC * HWS;
                *(float2*)(ob + (size_t)m1 * HWS + nn) =
                    make_float2(acc[mi][ni][0] + bv1, acc[mi][ni][1] + bv1);
                *(float2*)(ob + (size_t)m2 * HWS + nn) =
                    make_float2(acc[mi][ni][2] + bv2, acc[mi][ni][3] + bv2);
            } else {
                __nv_bfloat162* ob = (__nv_bfloat162*)g_botB + ((size_t)b * CC * HWS >> 1);
                ob[((size_t)m1 * HWS + nn) >> 1] =
                    __floats2bfloat162_rn(acc[mi][ni][0] + bv1, acc[mi][ni][1] + bv1);
                ob[((size_t)m2 * HWS + nn) >> 1] =
                    __floats2bfloat162_rn(acc[mi][ni][2] + bv2, acc[mi][ni][3] + bv2);
            }
        }
    }
}

// ---------------- S = cen @ top^T (fp16 hi/lo x3) + fused exp/sum ------------
__global__ void __launch_bounds__(256, 1) k_S_h()
{
    extern __shared__ uint32_t dynS[];    // Ah,Al,Bh,Bl each [128][32]u32 = 64KB
    uint32_t* Ah = dynS;
    uint32_t* Al = dynS + 4096;
    uint32_t* Bh = dynS + 8192;
    uint32_t* Bl = dynS + 12288;
    __shared__ float red[256];

    const int b   = blockIdx.z;
    const int n0  = blockIdx.x * 128;
    const int m0  = blockIdx.y * 128;
    const int tid = threadIdx.x;
    const int wid = tid >> 5, lane = tid & 31;
    const int warp_m = (wid & 1) * 64;
    const int warp_n = (wid >> 1) * 32;
    const int g = lane >> 2, t = lane & 3;

    // single-shot load: K=64 halves = 32 u32 per row, 4 panels
    {
        int r  = tid >> 1;
        int hf = tid & 1;
        size_t rowA = ((size_t)b * HWS + m0 + r) * 32;   // u32 units (PP/2)
        size_t rowB = ((size_t)b * HWS + n0 + r) * 32;
        const uint4* pAh = (const uint4*)((const uint32_t*)g_cenHh + rowA);
        const uint4* pAl = (const uint4*)((const uint32_t*)g_cenLh + rowA);
        const uint4* pBh = (const uint4*)((const uint32_t*)g_topHh + rowB);
        const uint4* pBl = (const uint4*)((const uint32_t*)g_topLh + rowB);
#pragma unroll
        for (int j = 0; j < 4; j++) {
            int cq = hf * 4 + j;
            int d  = r * 32 + ((cq ^ (r & 7)) << 2);
            *(uint4*)&Ah[d] = pAh[cq];
            *(uint4*)&Al[d] = pAl[cq];
            *(uint4*)&Bh[d] = pBh[cq];
            *(uint4*)&Bl[d] = pBl[cq];
        }
    }
    __syncthreads();

    float acc[4][4][4];
#pragma unroll
    for (int mi = 0; mi < 4; mi++)
#pragma unroll
        for (int ni = 0; ni < 4; ni++)
#pragma unroll
            for (int e = 0; e < 4; e++) acc[mi][ni][e] = 0.f;

    const uint32_t ahb = s2u(dynS);
    const uint32_t alb = ahb + 16384;
    const uint32_t bhb = ahb + 32768;
    const uint32_t blb = ahb + 49152;

    const int a_row = warp_m + (lane & 15);
    const int a_chk = (lane >> 4) << 2;
    const int b_row = warp_n + ((lane >> 4) << 3) + (lane & 7);
    const int b_chk = ((lane >> 3) & 1) << 2;

#pragma unroll
    for (int ks = 0; ks < 4; ks++) {
        int kb = ks * 8;
        uint32_t ah[4][4], al[4][4], bh[4][2], bl[4][2];
#pragma unroll
        for (int mi = 0; mi < 4; mi++) {
            uint32_t off = 4u * (uint32_t)sw32(a_row + mi * 16, kb + a_chk);
            LDSM4(ah[mi][0], ah[mi][1], ah[mi][2], ah[mi][3], ahb + off);
            LDSM4(al[mi][0], al[mi][1], al[mi][2], al[mi][3], alb + off);
        }
#pragma unroll
        for (int np = 0; np < 2; np++) {
            uint32_t off = 4u * (uint32_t)sw32(b_row + np * 16, kb + b_chk);
            LDSM4(bh[np*2][0], bh[np*2][1], bh[np*2+1][0], bh[np*2+1][1], bhb + off);
            LDSM4(bl[np*2][0], bl[np*2][1], bl[np*2+1][0], bl[np*2+1][1], blb + off);
        }
#pragma unroll
        for (int mi = 0; mi < 4; mi++)
#pragma unroll
            for (int ni = 0; ni < 4; ni++) {
                mma16(acc[mi][ni], ah[mi], bh[ni]);
                mma16(acc[mi][ni], ah[mi], bl[ni]);
                mma16(acc[mi][ni], al[mi], bh[ni]);
            }
    }

    // epilogue: E = bf16(exp(S - 40)); deterministic sum of the ROUNDED values
    __nv_bfloat162* Eb = (__nv_bfloat162*)(g_Eb + (size_t)b * HWS * HWS);
    float ls = 0.f;
#pragma unroll
    for (int mi = 0; mi < 4; mi++) {
        int m1 = m0 + warp_m + mi * 16 + g;
        int m2 = m1 + 8;
#pragma unroll
        for (int ni = 0; ni < 4; ni++) {
            int nn = n0 + warp_n + ni * 8 + 2 * t;
            __nv_bfloat16 h0 = __float2bfloat16(__expf(acc[mi][ni][0] - 40.f));
            __nv_bfloat16 h1 = __float2bfloat16(__expf(acc[mi][ni][1] - 40.f));
            __nv_bfloat16 h2 = __float2bfloat16(__expf(acc[mi][ni][2] - 40.f));
            __nv_bfloat16 h3 = __float2bfloat16(__expf(acc[mi][ni][3] - 40.f));
            ls += (__bfloat162float(h0) + __bfloat162float(h1)) +
                  (__bfloat162float(h2) + __bfloat162float(h3));
            Eb[((size_t)m1 * HWS + nn) >> 1] = __nv_bfloat162(h0, h1);
            Eb[((size_t)m2 * HWS + nn) >> 1] = __nv_bfloat162(h2, h3);
        }
    }
    red[tid] = ls;
    __syncthreads();
    for (int st = 128; st > 0; st >>= 1) {
        if (tid < st) red[tid] += red[tid + st];
        __syncthreads();
    }
    if (tid == 0) g_partialS[b * 1024 + blockIdx.y * 32 + blockIdx.x] = red[0];
}

// ---------------- reduce partial sums ----------------------------------------
__global__ void k_sumreduce()
{
    const int b = blockIdx.x;
    const int tid = threadIdx.x;
    __shared__ float red[256];
    float s = 0.f;
    for (int i = tid; i < 1024; i += 256) s += g_partialS[b * 1024 + i];
    red[tid] = s;
    __syncthreads();
    for (int st = 128; st > 0; st >>= 1) {
        if (tid < st) red[tid] += red[tid + st];
        __syncthreads();
    }
    if (tid == 0) g_sum[b] = red[0];
}

// ---------------- attn: (E/sum)@bottomT^T bf16, 4-stage; writes x+attn fp16 --
__global__ void __launch_bounds__(256, 2) k_attn_h(const float* __restrict__ x)
{
    extern __shared__ uint32_t sm[];   // 4 stages x (A 2048 + B 2048 u32) = 64KB
    const uint32_t smb = s2u(sm);

    const int b   = blockIdx.z;
    const int cb  = blockIdx.x * 128;   // C tile
    const int m0  = blockIdx.y * 128;   // HW tile
    const int tid = threadIdx.x;
    const int wid = tid >> 5, lane = tid & 31;
    const int warp_m = (wid & 1) * 64;
    const int warp_n = (wid >> 1) * 32;

    const int r  = tid >> 1;
    const int hf = tid & 1;

    const uint32_t* Arow = (const uint32_t*)g_Eb + ((size_t)b * HWS + m0 + r) * HWS2;
    const uint32_t* Brow = (const uint32_t*)g_botB + ((size_t)b * CC + cb + r) * HWS2;

    float acc[4][4][4];
#pragma unroll
    for (int mi = 0; mi < 4; mi++)
#pragma unroll
        for (int ni = 0; ni < 4; ni++)
#pragma unroll
            for (int e = 0; e < 4; e++) acc[mi][ni][e] = 0.f;

    auto issue_stage = [&](int c, int st) {
        uint32_t ab = smb + st * 16384;
        uint32_t bb = ab + 8192;
        int ku = c * 16;   // u32 offset of this k32 panel
#pragma unroll
        for (int j = 0; j < 2; j++) {
            int cq = hf * 2 + j;
            uint32_t off = 4u * (uint32_t)(r * 16 + ((cq ^ ((r >> 1) & 3)) << 2));
            cpa16(ab + off, Arow + ku + cq * 4);
            cpa16(bb + off, Brow + ku + cq * 4);
        }
    };

    const int NC = 128;
    issue_stage(0, 0); CP_COMMIT();
    issue_stage(1, 1); CP_COMMIT();
    issue_stage(2, 2); CP_COMMIT();

    for (int c = 0; c < NC; c++) {
        CP_WAIT(2);
        __syncthreads();
        int ip = (c + 3 < NC) ? c + 3 : 0;
        issue_stage(ip, (c + 3) & 3);
        CP_COMMIT();
        int st = c & 3;
        panel_mma16<true>(acc, smb + st * 16384, smb + st * 16384 + 8192, warp_m, warp_n, lane);
    }

    const int g = lane >> 2, t = lane & 3;
    const float inv = 1.0f / g_sum[b];
    const float* xb = x + (size_t)b * CC * HWS;
    __half* zb = g_xzh + (size_t)b * CC * HWS;

#pragma unroll
    for (int mi = 0; mi < 4; mi++) {
        int mrows[2] = { m0 + warp_m + mi * 16 + g, m0 + warp_m + mi * 16 + g + 8 };
#pragma unroll
        for (int ni = 0; ni < 4; ni++) {
            int nn = cb + warp_n + ni * 8 + 2 * t;
#pragma unroll
            for (int hrow = 0; hrow < 2; hrow++) {
                int f = mrows[hrow] * CC + nn;
                float2 xv = *(const float2*)(xb + f);
                float v0 = xv.x + acc[mi][ni][hrow * 2 + 0] * inv;
                float v1 = xv.y + acc[mi][ni][hrow * 2 + 1] * inv;
                // pair-interleaved store: element (c,hw) -> half idx ((c>>1)*HWS+hw)*2 + (c&1)
                int c0 = f >> 12,        hw0 = f & 4095;
                int c1 = (f + 1) >> 12,  hw1 = (f + 1) & 4095;
                zb[((size_t)(c0 >> 1) * HWS + hw0) * 2 + (c0 & 1)] = __float2half_rn(v0);
                zb[((size_t)(c1 >> 1) * HWS + hw1) * 2 + (c1 & 1)] = __float2half_rn(v1);
            }
        }
    }
}

// ---------------- launch -----------------------------------------------------
extern "C" void kernel_launch(void* const* d_in, const int* in_sizes, int n_in,
                              void* d_out, int out_size)
{
    const float* x   = (const float*)d_in[0];
    const float* wt  = (const float*)d_in[1];
    const float* bt  = (const float*)d_in[2];
    const float* wc  = (const float*)d_in[3];
    const float* bc  = (const float*)d_in[4];
    const float* wb  = (const float*)d_in[5];
    const float* bbm = (const float*)d_in[6];
    const float* wo  = (const float*)d_in[7];
    const float* bo  = (const float*)d_in[8];
    float* out = (float*)d_out;

    cudaFuncSetAttribute(k_conv_h<false>, cudaFuncAttributeMaxDynamicSharedMemorySize, 65536);
    cudaFuncSetAttribute(k_conv_h<true>,  cudaFuncAttributeMaxDynamicSharedMemorySize, 65536);
    cudaFuncSetAttribute(k_S_h,           cudaFuncAttributeMaxDynamicSharedMemorySize, 65536);
    cudaFuncSetAttribute(k_attn_h,        cudaFuncAttributeMaxDynamicSharedMemorySize, 65536);

    __half* d_wbh; cudaGetSymbolAddress((void**)&d_wbh, g_wbh);
    __half* d_woh; cudaGetSymbolAddress((void**)&d_woh, g_woh);

    k_xpack<<<(BB * 128 * HWS + 255) / 256, 256>>>(x);
    k_wtransH<<<(CC * 2304 + 255) / 256, 256>>>(wb, d_wbh);
    k_wtransH<<<(CC * 2304 + 255) / 256, 256>>>(wo, d_woh);

    k_top_center<<<dim3(HWS / 64, BB), 256>>>(x, wt, bt, wc, bc);
    k_conv_h<false><<<dim3(32, 2, BB), 256, 65536>>>(bbm, nullptr);
    k_S_h<<<dim3(32, 32, BB), 256, 65536>>>();
    k_sumreduce<<<BB, 256>>>();
    k_attn_h<<<dim3(2, 32, BB), 256, 65536>>>(x);
    k_conv_h<true><<<dim3(32, 2, BB), 256, 65536>>>(bo, out);
}

// round 16
// speedup vs baseline: 2.7763x; 1.0510x over previous
#include <cuda_runtime.h>
#include <cuda_fp16.h>
#include <cuda_bf16.h>
#include <cstdint>

#define BB  8
#define CC  256
#define PP  64
#define HWS 4096
#define HWS2 2048           // u32 (half2/bf162) per row of HWS 16-bit elems

// ---------------- scratch (device globals) -----------------------------------
__device__ __align__(128) __half g_xh  [BB * CC * HWS];   // x, channel-pair interleaved fp16
__device__ __align__(128) __half g_xzh [BB * CC * HWS];   // x + attn, pair interleaved fp16
__device__ __align__(128) __half g_wbh [CC * 2304];       // w_bottom [co][r3*256+ci] fp16
__device__ __align__(128) __half g_woh [CC * 2304];       // w_out    [co][r3*256+ci] fp16
__device__ __align__(128) __half g_topHh[BB * HWS * PP];  // hi ([B][HW][P]) fp16
__device__ __align__(128) __half g_topLh[BB * HWS * PP];  // lo
__device__ __align__(128) __half g_cenHh[BB * HWS * PP];
__device__ __align__(128) __half g_cenLh[BB * HWS * PP];
__device__ __align__(128) __nv_bfloat16 g_botB[BB * CC * HWS];        // bottomT [B][C][HW] bf16
__device__ __align__(128) __nv_bfloat16 g_Eb[(size_t)BB * HWS * HWS]; // E = exp(S-40) bf16, 268MB
__device__ float g_partialS[BB * 1024];
__device__ float g_sum[BB];

// ---------------- helpers ----------------------------------------------------
__device__ __forceinline__ void mma16(float* d, const uint32_t* a, const uint32_t* b) {
    asm volatile(
        "mma.sync.aligned.m16n8k16.row.col.f32.f16.f16.f32 "
        "{%0,%1,%2,%3}, {%4,%5,%6,%7}, {%8,%9}, {%0,%1,%2,%3};"
        : "+f"(d[0]), "+f"(d[1]), "+f"(d[2]), "+f"(d[3])
        : "r"(a[0]), "r"(a[1]), "r"(a[2]), "r"(a[3]), "r"(b[0]), "r"(b[1]));
}
__device__ __forceinline__ void mma16bf(float* d, const uint32_t* a, const uint32_t* b) {
    asm volatile(
        "mma.sync.aligned.m16n8k16.row.col.f32.bf16.bf16.f32 "
        "{%0,%1,%2,%3}, {%4,%5,%6,%7}, {%8,%9}, {%0,%1,%2,%3};"
        : "+f"(d[0]), "+f"(d[1]), "+f"(d[2]), "+f"(d[3])
        : "r"(a[0]), "r"(a[1]), "r"(a[2]), "r"(a[3]), "r"(b[0]), "r"(b[1]));
}
#define LDSM4(r0, r1, r2, r3, ad) \
    asm volatile("ldmatrix.sync.aligned.m8n8.x4.shared.b16 {%0,%1,%2,%3}, [%4];" \
        : "=r"(r0), "=r"(r1), "=r"(r2), "=r"(r3) : "r"(ad))

// swizzle: panels are [128 rows] x [16 u32] (64B rows)
__device__ __forceinline__ int sw16(int r, int c) {
    return r * 16 + ((((c >> 2) ^ ((r >> 1) & 3)) << 2)) + (c & 3);
}

__device__ __forceinline__ uint32_t s2u(const void* p) {
    uint32_t a;
    asm("{ .reg .u64 t; cvta.to.shared.u64 t, %1; cvt.u32.u64 %0, t; }" : "=r"(a) : "l"(p));
    return a;
}
__device__ __forceinline__ void cpa16(uint32_t dst, const void* src) {
    asm volatile("cp.async.cg.shared.global [%0], [%1], 16;" :: "r"(dst), "l"(src));
}
__device__ __forceinline__ void cpa4(uint32_t dst, const void* src) {
    asm volatile("cp.async.ca.shared.global [%0], [%1], 4;" :: "r"(dst), "l"(src));
}
#define CP_COMMIT() asm volatile("cp.async.commit_group;" ::: "memory")
#define CP_WAIT(N)  asm volatile("cp.async.wait_group %0;" :: "n"(N) : "memory")

// ---------------- warp compute: one k32 16-bit panel, ldmatrix loads ---------
template<bool BF>
__device__ __forceinline__ void panel_mma16(float acc[4][4][4],
                                            uint32_t smA, uint32_t smB,
                                            int warp_m, int warp_n, int lane) {
    const int a_row = warp_m + (lane & 15);
    const int a_chk = (lane >> 4) << 2;          // 0 or 4 (u32)
    const int b_row = warp_n + ((lane >> 4) << 3) + (lane & 7);
    const int b_chk = ((lane >> 3) & 1) << 2;    // 0 or 4
#pragma unroll
    for (int ks = 0; ks < 2; ks++) {
        int kb = ks * 8;
        uint32_t af[4][4], bf[4][2];
#pragma unroll
        for (int mi = 0; mi < 4; mi++) {
            uint32_t ad = smA + 4u * (uint32_t)sw16(a_row + mi * 16, kb + a_chk);
            LDSM4(af[mi][0], af[mi][1], af[mi][2], af[mi][3], ad);
        }
#pragma unroll
        for (int np = 0; np < 2; np++) {
            uint32_t bd = smB + 4u * (uint32_t)sw16(b_row + np * 16, kb + b_chk);
            LDSM4(bf[np*2][0], bf[np*2][1], bf[np*2+1][0], bf[np*2+1][1], bd);
        }
#pragma unroll
        for (int mi = 0; mi < 4; mi++)
#pragma unroll
            for (int ni = 0; ni < 4; ni++) {
                if (BF) mma16bf(acc[mi][ni], af[mi], bf[ni]);
                else    mma16  (acc[mi][ni], af[mi], bf[ni]);
            }
    }
}

// ---------------- K0: weight reorder+fp16, both weights in one launch --------
__global__ void k_wtransH2(const float* __restrict__ wb, const float* __restrict__ wo) {
    int i = blockIdx.x * 256 + threadIdx.x;
    if (i < 2 * CC * 2304) {
        int which = i >= CC * 2304;
        int ii  = which ? i - CC * 2304 : i;
        int co  = ii / 2304;
        int rem = ii - co * 2304;
        int r3  = rem >> 8;
        int ci  = rem & 255;
        const float* w = which ? wo : wb;
        __half* d = which ? g_woh : g_wbh;
        d[ii] = __float2half_rn(w[co * 2304 + ci * 9 + r3]);
    }
}

// ---------------- K1: 1x1 convs -> top/center fp16 hi+lo; also packs x -------
__global__ void k_top_center(const float* __restrict__ x,
                             const float* __restrict__ wt, const float* __restrict__ bt,
                             const float* __restrict__ wc, const float* __restrict__ bc)
{
    const int b  = blockIdx.y;
    const int n0 = blockIdx.x * 64;
    const int t  = threadIdx.x;
    const int p  = t & 63;
    const int q  = t >> 6;

    __shared__ float xs[16][64];
    __shared__ float wts[64][17];
    __shared__ float wcs[64][17];

    float acct[16], accc[16];
#pragma unroll
    for (int j = 0; j < 16; j++) { acct[j] = 0.f; accc[j] = 0.f; }

    const float* xb = x + (size_t)b * CC * HWS;
    __half2* xpk = (__half2*)g_xh + (size_t)b * 128 * HWS;

    for (int c0 = 0; c0 < CC; c0 += 16) {
        {
            int cc = t >> 4;
            int nn = (t & 15) * 4;
            float4 v = *(const float4*)(xb + (size_t)(c0 + cc) * HWS + n0 + nn);
            *(float4*)&xs[cc][nn] = v;
        }
        {
            int p_ = t >> 2;
            int cq = (t & 3) * 4;
            float4 v = *(const float4*)(wt + (size_t)p_ * CC + c0 + cq);
            wts[p_][cq + 0] = v.x; wts[p_][cq + 1] = v.y; wts[p_][cq + 2] = v.z; wts[p_][cq + 3] = v.w;
            float4 u = *(const float4*)(wc + (size_t)p_ * CC + c0 + cq);
            wcs[p_][cq + 0] = u.x; wcs[p_][cq + 1] = u.y; wcs[p_][cq + 2] = u.z; wcs[p_][cq + 3] = u.w;
        }
        __syncthreads();
        // side-output: fp16 pair-interleaved copy of this x tile (replaces k_xpack)
        {
#pragma unroll
            for (int u2 = 0; u2 < 2; u2++) {
                int idx = t * 2 + u2;          // 0..511
                int pi  = idx >> 6;            // pair 0..7
                int hw  = idx & 63;
                __half2 v = __floats2half2_rn(xs[pi * 2][hw], xs[pi * 2 + 1][hw]);
                xpk[(size_t)((c0 >> 1) + pi) * HWS + n0 + hw] = v;
            }
        }
#pragma unroll
        for (int cc = 0; cc < 16; cc++) {
            float at = wts[p][cc];
            float ac = wcs[p][cc];
#pragma unroll
            for (int j = 0; j < 16; j++) {
                float xv = xs[cc][q * 16 + j];
                acct[j] += at * xv;
                accc[j] += ac * xv;
            }
        }
        __syncthreads();
    }

    const float btv = bt[p];
    const float bcv = bc[p];
    size_t base = (size_t)b * HWS * PP + (size_t)(n0 + q * 16) * PP + p;
#pragma unroll
    for (int j = 0; j < 16; j++) {
        float vt = acct[j] + btv;
        float vc = accc[j] + bcv;
        __half th = __float2half_rn(vt);
        __half tl = __float2half_rn(vt - __half2float(th));
        __half ch = __float2half_rn(vc);
        __half cl = __float2half_rn(vc - __half2float(ch));
        size_t o = base + (size_t)j * PP;
        g_topHh[o] = th; g_topLh[o] = tl;
        g_cenHh[o] = ch; g_cenLh[o] = cl;
    }
}

// ---------------- conv 3x3: fp16 implicit GEMM, 4-stage cp.async ring --------
// K order [r3][ci]; B source = pair-interleaved fp16 image.
template<bool ADDZ>
__global__ void __launch_bounds__(256, 2)
k_conv_h(const float* __restrict__ bias, float* __restrict__ outp)
{
    extern __shared__ uint32_t sm[];   // 4 stages x (A 2048 + B 2048 u32) = 64KB
    const uint32_t smb = s2u(sm);

    const int b   = blockIdx.z;
    const int n0  = blockIdx.x * 128;
    const int m0  = blockIdx.y * 128;
    const int tid = threadIdx.x;
    const int wid = tid >> 5, lane = tid & 31;
    const int warp_m = (wid & 1) * 64;
    const int warp_n = (wid >> 1) * 32;

    const int r  = tid >> 1;
    const int hf = tid & 1;
    const int n  = n0 + r;
    const int h  = n >> 6, w = n & 63;

    const uint32_t* xbase = (const uint32_t*)(ADDZ ? g_xzh : g_xh) + (size_t)b * 128 * HWS;
    const uint32_t* arow  = (const uint32_t*)(ADDZ ? g_woh : g_wbh) + (size_t)(m0 + r) * 1152;

    float acc[4][4][4];
#pragma unroll
    for (int mi = 0; mi < 4; mi++)
#pragma unroll
        for (int ni = 0; ni < 4; ni++)
#pragma unroll
            for (int e = 0; e < 4; e++) acc[mi][ni][e] = 0.f;

    auto issue_stage = [&](int c, int st) {
        uint32_t ab = smb + st * 16384;
        uint32_t bb = ab + 8192;
        int k0 = c * 32;
        const uint32_t* ar = arow + (k0 >> 1);
#pragma unroll
        for (int j = 0; j < 2; j++) {
            int cq = hf * 2 + j;
            cpa16(ab + 4u * (uint32_t)(r * 16 + ((cq ^ ((r >> 1) & 3)) << 2)), ar + cq * 4);
        }
        int r3  = k0 >> 8;
        int cp0 = (k0 & 255) >> 1;
        int dh  = r3 / 3 - 1;
        int dw  = r3 - (r3 / 3) * 3 - 1;
        int hh = h + dh, ww = w + dw;
        if ((unsigned)hh < 64u && (unsigned)ww < 64u) {
            const uint32_t* src = xbase + (size_t)cp0 * HWS + hh * 64 + ww;
#pragma unroll
            for (int j = 0; j < 8; j++) {
                int c4 = hf * 8 + j;
                uint32_t off = 4u * (uint32_t)sw16(r, c4);
                cpa4(bb + off, src + (size_t)c4 * HWS);
            }
        } else {
            uint32_t* bz = sm + st * 4096 + 2048;
#pragma unroll
            for (int j = 0; j < 2; j++) {
                int cq = hf * 2 + j;
                *(uint4*)&bz[r * 16 + ((cq ^ ((r >> 1) & 3)) << 2)] = make_uint4(0, 0, 0, 0);
            }
        }
    };

    const int NC = 72;
    issue_stage(0, 0); CP_COMMIT();
    issue_stage(1, 1); CP_COMMIT();
    issue_stage(2, 2); CP_COMMIT();

    for (int c = 0; c < NC; c++) {
        CP_WAIT(2);
        __syncthreads();
        int ip = (c + 3 < NC) ? c + 3 : 0;     // dummy re-issue keeps group count exact
        issue_stage(ip, (c + 3) & 3);
        CP_COMMIT();
        int st = c & 3;
        panel_mma16<false>(acc, smb + st * 16384, smb + st * 16384 + 8192, warp_m, warp_n, lane);
    }

    const int g = lane >> 2, t = lane & 3;
#pragma unroll
    for (int mi = 0; mi < 4; mi++) {
        int m1 = m0 + warp_m + mi * 16 + g;
        int m2 = m1 + 8;
        float bv1 = bias[m1], bv2 = bias[m2];
#pragma unroll
        for (int ni = 0; ni < 4; ni++) {
            int nn = n0 + warp_n + ni * 8 + 2 * t;
            if (ADDZ) {
                float* ob = outp + (size_t)b * CC * HWS;
                *(float2*)(ob + (size_t)m1 * HWS + nn) =
                    make_float2(acc[mi][ni][0] + bv1, acc[mi][ni][1] + bv1);
                *(float2*)(ob + (size_t)m2 * HWS + nn) =
                    make_float2(acc[mi][ni][2] + bv2, acc[mi][ni][3] + bv2);
            } else {
                __nv_bfloat162* ob = (__nv_bfloat162*)g_botB + ((size_t)b * CC * HWS >> 1);
                ob[((size_t)m1 * HWS + nn) >> 1] =
                    __floats2bfloat162_rn(acc[mi][ni][0] + bv1, acc[mi][ni][1] + bv1);
                ob[((size_t)m2 * HWS + nn) >> 1] =
                    __floats2bfloat162_rn(acc[mi][ni][2] + bv2, acc[mi][ni][3] + bv2);
            }
        }
    }
}

// ---------------- S = cen @ top^T (fp16 hi/lo x3), 32KB smem (occ 2) ---------
// K=64 processed as two 32-col chunks through 4x8KB panels. Same k-order and
// mma sequence as before -> bitwise-identical accumulators.
__global__ void __launch_bounds__(256, 2) k_S_h()
{
    __shared__ uint32_t pan[8192];   // Ah | Al | Bh | Bl, 2048 u32 (8KB) each
    __shared__ float red[256];

    const int b   = blockIdx.z;
    const int n0  = blockIdx.x * 128;
    const int m0  = blockIdx.y * 128;
    const int tid = threadIdx.x;
    const int wid = tid >> 5, lane = tid & 31;
    const int warp_m = (wid & 1) * 64;
    const int warp_n = (wid >> 1) * 32;
    const int g = lane >> 2, t = lane & 3;
    const int r  = tid >> 1;
    const int hf = tid & 1;

    float acc[4][4][4];
#pragma unroll
    for (int mi = 0; mi < 4; mi++)
#pragma unroll
        for (int ni = 0; ni < 4; ni++)
#pragma unroll
            for (int e = 0; e < 4; e++) acc[mi][ni][e] = 0.f;

    const uint32_t pb  = s2u(pan);
    const uint32_t ahb = pb, alb = pb + 8192, bhb = pb + 16384, blb = pb + 24576;

    const int a_row = warp_m + (lane & 15);
    const int a_chk = (lane >> 4) << 2;
    const int b_row = warp_n + ((lane >> 4) << 3) + (lane & 7);
    const int b_chk = ((lane >> 3) & 1) << 2;

    for (int chk = 0; chk < 2; chk++) {
        __syncthreads();
        {
            size_t rowA = ((size_t)b * HWS + m0 + r) * 32 + chk * 16;   // u32 units
            size_t rowB = ((size_t)b * HWS + n0 + r) * 32 + chk * 16;
            const uint4* pAh = (const uint4*)((const uint32_t*)g_cenHh + rowA);
            const uint4* pAl = (const uint4*)((const uint32_t*)g_cenLh + rowA);
            const uint4* pBh = (const uint4*)((const uint32_t*)g_topHh + rowB);
            const uint4* pBl = (const uint4*)((const uint32_t*)g_topLh + rowB);
#pragma unroll
            for (int j = 0; j < 2; j++) {
                int cq = hf * 2 + j;
                int d  = r * 16 + ((cq ^ ((r >> 1) & 3)) << 2);
                *(uint4*)&pan[d]        = pAh[cq];
                *(uint4*)&pan[2048 + d] = pAl[cq];
                *(uint4*)&pan[4096 + d] = pBh[cq];
                *(uint4*)&pan[6144 + d] = pBl[cq];
            }
        }
        __syncthreads();
#pragma unroll
        for (int ks = 0; ks < 2; ks++) {
            int kb = ks * 8;
            uint32_t ah[4][4], al[4][4], bh[4][2], bl[4][2];
#pragma unroll
            for (int mi = 0; mi < 4; mi++) {
                uint32_t off = 4u * (uint32_t)sw16(a_row + mi * 16, kb + a_chk);
                LDSM4(ah[mi][0], ah[mi][1], ah[mi][2], ah[mi][3], ahb + off);
                LDSM4(al[mi][0], al[mi][1], al[mi][2], al[mi][3], alb + off);
            }
#pragma unroll
            for (int np = 0; np < 2; np++) {
                uint32_t off = 4u * (uint32_t)sw16(b_row + np * 16, kb + b_chk);
                LDSM4(bh[np*2][0], bh[np*2][1], bh[np*2+1][0], bh[np*2+1][1], bhb + off);
                LDSM4(bl[np*2][0], bl[np*2][1], bl[np*2+1][0], bl[np*2+1][1], blb + off);
            }
#pragma unroll
            for (int mi = 0; mi < 4; mi++)
#pragma unroll
                for (int ni = 0; ni < 4; ni++) {
                    mma16(acc[mi][ni], ah[mi], bh[ni]);
                    mma16(acc[mi][ni], ah[mi], bl[ni]);
                    mma16(acc[mi][ni], al[mi], bh[ni]);
                }
        }
    }

    // epilogue: E = bf16(exp(S - 40)); deterministic sum of the ROUNDED values
    __nv_bfloat162* Eb = (__nv_bfloat162*)(g_Eb + (size_t)b * HWS * HWS);
    float ls = 0.f;
#pragma unroll
    for (int mi = 0; mi < 4; mi++) {
        int m1 = m0 + warp_m + mi * 16 + g;
        int m2 = m1 + 8;
#pragma unroll
        for (int ni = 0; ni < 4; ni++) {
            int nn = n0 + warp_n + ni * 8 + 2 * t;
            __nv_bfloat16 h0 = __float2bfloat16(__expf(acc[mi][ni][0] - 40.f));
            __nv_bfloat16 h1 = __float2bfloat16(__expf(acc[mi][ni][1] - 40.f));
            __nv_bfloat16 h2 = __float2bfloat16(__expf(acc[mi][ni][2] - 40.f));
            __nv_bfloat16 h3 = __float2bfloat16(__expf(acc[mi][ni][3] - 40.f));
            ls += (__bfloat162float(h0) + __bfloat162float(h1)) +
                  (__bfloat162float(h2) + __bfloat162float(h3));
            Eb[((size_t)m1 * HWS + nn) >> 1] = __nv_bfloat162(h0, h1);
            Eb[((size_t)m2 * HWS + nn) >> 1] = __nv_bfloat162(h2, h3);
        }
    }
    red[tid] = ls;
    __syncthreads();
    for (int st = 128; st > 0; st >>= 1) {
        if (tid < st) red[tid] += red[tid + st];
        __syncthreads();
    }
    if (tid == 0) g_partialS[b * 1024 + blockIdx.y * 32 + blockIdx.x] = red[0];
}

// ---------------- reduce partial sums ----------------------------------------
__global__ void k_sumreduce()
{
    const int b = blockIdx.x;
    const int tid = threadIdx.x;
    __shared__ float red[256];
    float s = 0.f;
    for (int i = tid; i < 1024; i += 256) s += g_partialS[b * 1024 + i];
    red[tid] = s;
    __syncthreads();
    for (int st = 128; st > 0; st >>= 1) {
        if (tid < st) red[tid] += red[tid + st];
        __syncthreads();
    }
    if (tid == 0) g_sum[b] = red[0];
}

// ---------------- attn: (E/sum)@bottomT^T bf16, 4-stage; writes x+attn fp16 --
__global__ void __launch_bounds__(256, 2) k_attn_h(const float* __restrict__ x)
{
    extern __shared__ uint32_t sm[];   // 4 stages x (A 2048 + B 2048 u32) = 64KB
    const uint32_t smb = s2u(sm);

    const int b   = blockIdx.z;
    const int cb  = blockIdx.x * 128;   // C tile
    const int m0  = blockIdx.y * 128;   // HW tile
    const int tid = threadIdx.x;
    const int wid = tid >> 5, lane = tid & 31;
    const int warp_m = (wid & 1) * 64;
    const int warp_n = (wid >> 1) * 32;

    const int r  = tid >> 1;
    const int hf = tid & 1;

    const uint32_t* Arow = (const uint32_t*)g_Eb + ((size_t)b * HWS + m0 + r) * HWS2;
    const uint32_t* Brow = (const uint32_t*)g_botB + ((size_t)b * CC + cb + r) * HWS2;

    float acc[4][4][4];
#pragma unroll
    for (int mi = 0; mi < 4; mi++)
#pragma unroll
        for (int ni = 0; ni < 4; ni++)
#pragma unroll
            for (int e = 0; e < 4; e++) acc[mi][ni][e] = 0.f;

    auto issue_stage = [&](int c, int st) {
        uint32_t ab = smb + st * 16384;
        uint32_t bb = ab + 8192;
        int ku = c * 16;   // u32 offset of this k32 panel
#pragma unroll
        for (int j = 0; j < 2; j++) {
            int cq = hf * 2 + j;
            uint32_t off = 4u * (uint32_t)(r * 16 + ((cq ^ ((r >> 1) & 3)) << 2));
            cpa16(ab + off, Arow + ku + cq * 4);
            cpa16(bb + off, Brow + ku + cq * 4);
        }
    };

    const int NC = 128;
    issue_stage(0, 0); CP_COMMIT();
    issue_stage(1, 1); CP_COMMIT();
    issue_stage(2, 2); CP_COMMIT();

    for (int c = 0; c < NC; c++) {
        CP_WAIT(2);
        __syncthreads();
        int ip = (c + 3 < NC) ? c + 3 : 0;
        issue_stage(ip, (c + 3) & 3);
        CP_COMMIT();
        int st = c & 3;
        panel_mma16<true>(acc, smb + st * 16384, smb + st * 16384 + 8192, warp_m, warp_n, lane);
    }

    const int g = lane >> 2, t = lane & 3;
    const float inv = 1.0f / g_sum[b];
    const float* xb = x + (size_t)b * CC * HWS;
    __half* zb = g_xzh + (size_t)b * CC * HWS;

#pragma unroll
    for (int mi = 0; mi < 4; mi++) {
        int mrows[2] = { m0 + warp_m + mi * 16 + g, m0 + warp_m + mi * 16 + g + 8 };
#pragma unroll
        for (int ni = 0; ni < 4; ni++) {
            int nn = cb + warp_n + ni * 8 + 2 * t;
#pragma unroll
            for (int hrow = 0; hrow < 2; hrow++) {
                int f = mrows[hrow] * CC + nn;
                float2 xv = *(const float2*)(xb + f);
                float v0 = xv.x + acc[mi][ni][hrow * 2 + 0] * inv;
                float v1 = xv.y + acc[mi][ni][hrow * 2 + 1] * inv;
                // pair-interleaved store: element (c,hw) -> half idx ((c>>1)*HWS+hw)*2 + (c&1)
                int c0 = f >> 12,        hw0 = f & 4095;
                int c1 = (f + 1) >> 12,  hw1 = (f + 1) & 4095;
                zb[((size_t)(c0 >> 1) * HWS + hw0) * 2 + (c0 & 1)] = __float2half_rn(v0);
                zb[((size_t)(c1 >> 1) * HWS + hw1) * 2 + (c1 & 1)] = __float2half_rn(v1);
            }
        }
    }
}

// ---------------- launch -----------------------------------------------------
extern "C" void kernel_launch(void* const* d_in, const int* in_sizes, int n_in,
                              void* d_out, int out_size)
{
    const float* x   = (const float*)d_in[0];
    const float* wt  = (const float*)d_in[1];
    const float* bt  = (const float*)d_in[2];
    const float* wc  = (const float*)d_in[3];
    const float* bc  = (const float*)d_in[4];
    const float* wb  = (const float*)d_in[5];
    const float* bbm = (const float*)d_in[6];
    const float* wo  = (const float*)d_in[7];
    const float* bo  = (const float*)d_in[8];
    float* out = (float*)d_out;

    cudaFuncSetAttribute(k_conv_h<false>, cudaFuncAttributeMaxDynamicSharedMemorySize, 65536);
    cudaFuncSetAttribute(k_conv_h<true>,  cudaFuncAttributeMaxDynamicSharedMemorySize, 65536);
    cudaFuncSetAttribute(k_attn_h,        cudaFuncAttributeMaxDynamicSharedMemorySize, 65536);

    k_wtransH2<<<(2 * CC * 2304 + 255) / 256, 256>>>(wb, wo);
    k_top_center<<<dim3(HWS / 64, BB), 256>>>(x, wt, bt, wc, bc);
    k_conv_h<false><<<dim3(32, 2, BB), 256, 65536>>>(bbm, nullptr);
    k_S_h<<<dim3(32, 32, BB), 256>>>();
    k_sumreduce<<<BB, 256>>>();
    k_attn_h<<<dim3(2, 32, BB), 256, 65536>>>(x);
    k_conv_h<true><<<dim3(32, 2, BB), 256, 65536>>>(bo, out);
}

// round 17
// speedup vs baseline: 2.8137x; 1.0135x over previous
#include <cuda_runtime.h>
#include <cuda_fp16.h>
#include <cuda_bf16.h>
#include <cstdint>

#define BB  8
#define CC  256
#define PP  64
#define HWS 4096
#define HWS2 2048           // u32 (half2/bf162) per row of HWS 16-bit elems

// ---------------- scratch (device globals) -----------------------------------
// x / x+attn stored 8-channel-interleaved: [B][C/8][HW][8] fp16 (16B per (grp,pixel))
__device__ __align__(128) __half g_xh  [BB * CC * HWS];
__device__ __align__(128) __half g_xzh [BB * CC * HWS];
__device__ __align__(128) __half g_wbh [CC * 2304];       // w_bottom [co][r3*256+ci] fp16
__device__ __align__(128) __half g_woh [CC * 2304];       // w_out    [co][r3*256+ci] fp16
__device__ __align__(128) __half g_topHh[BB * HWS * PP];  // hi ([B][HW][P]) fp16
__device__ __align__(128) __half g_topLh[BB * HWS * PP];  // lo
__device__ __align__(128) __half g_cenHh[BB * HWS * PP];
__device__ __align__(128) __half g_cenLh[BB * HWS * PP];
__device__ __align__(128) __nv_bfloat16 g_botB[BB * CC * HWS];        // bottomT [B][C][HW] bf16
__device__ __align__(128) __nv_bfloat16 g_Eb[(size_t)BB * HWS * HWS]; // E = exp(S-40) bf16
__device__ float g_partialS[BB * 1024];
__device__ float g_sum[BB];

// ---------------- helpers ----------------------------------------------------
__device__ __forceinline__ void mma16(float* d, const uint32_t* a, const uint32_t* b) {
    asm volatile(
        "mma.sync.aligned.m16n8k16.row.col.f32.f16.f16.f32 "
        "{%0,%1,%2,%3}, {%4,%5,%6,%7}, {%8,%9}, {%0,%1,%2,%3};"
        : "+f"(d[0]), "+f"(d[1]), "+f"(d[2]), "+f"(d[3])
        : "r"(a[0]), "r"(a[1]), "r"(a[2]), "r"(a[3]), "r"(b[0]), "r"(b[1]));
}
__device__ __forceinline__ void mma16bf(float* d, const uint32_t* a, const uint32_t* b) {
    asm volatile(
        "mma.sync.aligned.m16n8k16.row.col.f32.bf16.bf16.f32 "
        "{%0,%1,%2,%3}, {%4,%5,%6,%7}, {%8,%9}, {%0,%1,%2,%3};"
        : "+f"(d[0]), "+f"(d[1]), "+f"(d[2]), "+f"(d[3])
        : "r"(a[0]), "r"(a[1]), "r"(a[2]), "r"(a[3]), "r"(b[0]), "r"(b[1]));
}
#define LDSM4(r0, r1, r2, r3, ad) \
    asm volatile("ldmatrix.sync.aligned.m8n8.x4.shared.b16 {%0,%1,%2,%3}, [%4];" \
        : "=r"(r0), "=r"(r1), "=r"(r2), "=r"(r3) : "r"(ad))

// swizzle: panels are [128 rows] x [16 u32] (64B rows)
__device__ __forceinline__ int sw16(int r, int c) {
    return r * 16 + ((((c >> 2) ^ ((r >> 1) & 3)) << 2)) + (c & 3);
}

__device__ __forceinline__ uint32_t s2u(const void* p) {
    uint32_t a;
    asm("{ .reg .u64 t; cvta.to.shared.u64 t, %1; cvt.u32.u64 %0, t; }" : "=r"(a) : "l"(p));
    return a;
}
__device__ __forceinline__ void cpa16(uint32_t dst, const void* src) {
    asm volatile("cp.async.cg.shared.global [%0], [%1], 16;" :: "r"(dst), "l"(src));
}
#define CP_COMMIT() asm volatile("cp.async.commit_group;" ::: "memory")
#define CP_WAIT(N)  asm volatile("cp.async.wait_group %0;" :: "n"(N) : "memory")

// ---------------- warp compute: one k32 16-bit panel, ldmatrix loads ---------
template<bool BF>
__device__ __forceinline__ void panel_mma16(float acc[4][4][4],
                                            uint32_t smA, uint32_t smB,
                                            int warp_m, int warp_n, int lane) {
    const int a_row = warp_m + (lane & 15);
    const int a_chk = (lane >> 4) << 2;          // 0 or 4 (u32)
    const int b_row = warp_n + ((lane >> 4) << 3) + (lane & 7);
    const int b_chk = ((lane >> 3) & 1) << 2;    // 0 or 4
#pragma unroll
    for (int ks = 0; ks < 2; ks++) {
        int kb = ks * 8;
        uint32_t af[4][4], bf[4][2];
#pragma unroll
        for (int mi = 0; mi < 4; mi++) {
            uint32_t ad = smA + 4u * (uint32_t)sw16(a_row + mi * 16, kb + a_chk);
            LDSM4(af[mi][0], af[mi][1], af[mi][2], af[mi][3], ad);
        }
#pragma unroll
        for (int np = 0; np < 2; np++) {
            uint32_t bd = smB + 4u * (uint32_t)sw16(b_row + np * 16, kb + b_chk);
            LDSM4(bf[np*2][0], bf[np*2][1], bf[np*2+1][0], bf[np*2+1][1], bd);
        }
#pragma unroll
        for (int mi = 0; mi < 4; mi++)
#pragma unroll
            for (int ni = 0; ni < 4; ni++) {
                if (BF) mma16bf(acc[mi][ni], af[mi], bf[ni]);
                else    mma16  (acc[mi][ni], af[mi], bf[ni]);
            }
    }
}

// ---------------- K0: weight reorder+fp16, both weights in one launch --------
__global__ void k_wtransH2(const float* __restrict__ wb, const float* __restrict__ wo) {
    int i = blockIdx.x * 256 + threadIdx.x;
    if (i < 2 * CC * 2304) {
        int which = i >= CC * 2304;
        int ii  = which ? i - CC * 2304 : i;
        int co  = ii / 2304;
        int rem = ii - co * 2304;
        int r3  = rem >> 8;
        int ci  = rem & 255;
        const float* w = which ? wo : wb;
        __half* d = which ? g_woh : g_wbh;
        d[ii] = __float2half_rn(w[co * 2304 + ci * 9 + r3]);
    }
}

// ---------------- K1: 1x1 convs -> top/center fp16 hi+lo; packs x 8-interleave
__global__ void k_top_center(const float* __restrict__ x,
                             const float* __restrict__ wt, const float* __restrict__ bt,
                             const float* __restrict__ wc, const float* __restrict__ bc)
{
    const int b  = blockIdx.y;
    const int n0 = blockIdx.x * 64;
    const int t  = threadIdx.x;
    const int p  = t & 63;
    const int q  = t >> 6;

    __shared__ float xs[16][64];
    __shared__ float wts[64][17];
    __shared__ float wcs[64][17];

    float acct[16], accc[16];
#pragma unroll
    for (int j = 0; j < 16; j++) { acct[j] = 0.f; accc[j] = 0.f; }

    const float* xb = x + (size_t)b * CC * HWS;
    uint4* xpk = (uint4*)g_xh + (size_t)b * 32 * HWS;   // [grp][hw] 16B units

    for (int c0 = 0; c0 < CC; c0 += 16) {
        {
            int cc = t >> 4;
            int nn = (t & 15) * 4;
            float4 v = *(const float4*)(xb + (size_t)(c0 + cc) * HWS + n0 + nn);
            *(float4*)&xs[cc][nn] = v;
        }
        {
            int p_ = t >> 2;
            int cq = (t & 3) * 4;
            float4 v = *(const float4*)(wt + (size_t)p_ * CC + c0 + cq);
            wts[p_][cq + 0] = v.x; wts[p_][cq + 1] = v.y; wts[p_][cq + 2] = v.z; wts[p_][cq + 3] = v.w;
            float4 u = *(const float4*)(wc + (size_t)p_ * CC + c0 + cq);
            wcs[p_][cq + 0] = u.x; wcs[p_][cq + 1] = u.y; wcs[p_][cq + 2] = u.z; wcs[p_][cq + 3] = u.w;
        }
        __syncthreads();
        // side-output: 8-channel-interleaved fp16 copy of this x tile
        if (t < 128) {
            int gi = t >> 6;           // 0..1 (two groups of 8 in this 16-ch tile)
            int hw = t & 63;
            __half2 p0 = __floats2half2_rn(xs[gi*8+0][hw], xs[gi*8+1][hw]);
            __half2 p1 = __floats2half2_rn(xs[gi*8+2][hw], xs[gi*8+3][hw]);
            __half2 p2 = __floats2half2_rn(xs[gi*8+4][hw], xs[gi*8+5][hw]);
            __half2 p3 = __floats2half2_rn(xs[gi*8+6][hw], xs[gi*8+7][hw]);
            uint4 v;
            v.x = *(uint32_t*)&p0; v.y = *(uint32_t*)&p1;
            v.z = *(uint32_t*)&p2; v.w = *(uint32_t*)&p3;
            xpk[(size_t)((c0 >> 3) + gi) * HWS + n0 + hw] = v;
        }
#pragma unroll
        for (int cc = 0; cc < 16; cc++) {
            float at = wts[p][cc];
            float ac = wcs[p][cc];
#pragma unroll
            for (int j = 0; j < 16; j++) {
                float xv = xs[cc][q * 16 + j];
                acct[j] += at * xv;
                accc[j] += ac * xv;
            }
        }
        __syncthreads();
    }

    const float btv = bt[p];
    const float bcv = bc[p];
    size_t base = (size_t)b * HWS * PP + (size_t)(n0 + q * 16) * PP + p;
#pragma unroll
    for (int j = 0; j < 16; j++) {
        float vt = acct[j] + btv;
        float vc = accc[j] + bcv;
        __half th = __float2half_rn(vt);
        __half tl = __float2half_rn(vt - __half2float(th));
        __half ch = __float2half_rn(vc);
        __half cl = __float2half_rn(vc - __half2float(ch));
        size_t o = base + (size_t)j * PP;
        g_topHh[o] = th; g_topLh[o] = tl;
        g_cenHh[o] = ch; g_cenLh[o] = cl;
    }
}

// ---------------- conv 3x3: fp16 implicit GEMM, 4-stage cp.async ring --------
// K order [r3][ci]; B source = 8-channel-interleaved image -> 2 cpa16/thread.
template<bool ADDZ>
__global__ void __launch_bounds__(256, 2)
k_conv_h(const float* __restrict__ bias, float* __restrict__ outp)
{
    extern __shared__ uint32_t sm[];   // 4 stages x (A 2048 + B 2048 u32) = 64KB
    const uint32_t smb = s2u(sm);

    const int b   = blockIdx.z;
    const int n0  = blockIdx.x * 128;
    const int m0  = blockIdx.y * 128;
    const int tid = threadIdx.x;
    const int wid = tid >> 5, lane = tid & 31;
    const int warp_m = (wid & 1) * 64;
    const int warp_n = (wid >> 1) * 32;

    const int r  = tid >> 1;
    const int hf = tid & 1;
    const int n  = n0 + r;
    const int h  = n >> 6, w = n & 63;

    const uint4* x8 = (const uint4*)(ADDZ ? g_xzh : g_xh) + (size_t)b * 32 * HWS;
    const uint32_t* arow = (const uint32_t*)(ADDZ ? g_woh : g_wbh) + (size_t)(m0 + r) * 1152;

    float acc[4][4][4];
#pragma unroll
    for (int mi = 0; mi < 4; mi++)
#pragma unroll
        for (int ni = 0; ni < 4; ni++)
#pragma unroll
            for (int e = 0; e < 4; e++) acc[mi][ni][e] = 0.f;

    auto issue_stage = [&](int c, int st) {
        uint32_t ab = smb + st * 16384;
        uint32_t bb = ab + 8192;
        int k0 = c * 32;
        const uint32_t* ar = arow + (k0 >> 1);
#pragma unroll
        for (int j = 0; j < 2; j++) {
            int cq = hf * 2 + j;
            cpa16(ab + 4u * (uint32_t)(r * 16 + ((cq ^ ((r >> 1) & 3)) << 2)), ar + cq * 4);
        }
        int r3  = k0 >> 8;
        int gq0 = (k0 & 255) >> 3;      // starting channel-group
        int dh  = r3 / 3 - 1;
        int dw  = r3 - (r3 / 3) * 3 - 1;
        int hh = h + dh, ww = w + dw;
        if ((unsigned)hh < 64u && (unsigned)ww < 64u) {
            const uint4* src = x8 + (size_t)gq0 * HWS + hh * 64 + ww;
#pragma unroll
            for (int j = 0; j < 2; j++) {
                int cq = hf * 2 + j;
                cpa16(bb + 4u * (uint32_t)(r * 16 + ((cq ^ ((r >> 1) & 3)) << 2)),
                      src + (size_t)cq * HWS);
            }
        } else {
            uint32_t* bz = sm + st * 4096 + 2048;
#pragma unroll
            for (int j = 0; j < 2; j++) {
                int cq = hf * 2 + j;
                *(uint4*)&bz[r * 16 + ((cq ^ ((r >> 1) & 3)) << 2)] = make_uint4(0, 0, 0, 0);
            }
        }
    };

    const int NC = 72;
    issue_stage(0, 0); CP_COMMIT();
    issue_stage(1, 1); CP_COMMIT();
    issue_stage(2, 2); CP_COMMIT();

    for (int c = 0; c < NC; c++) {
        CP_WAIT(2);
        __syncthreads();
        int ip = (c + 3 < NC) ? c + 3 : 0;     // dummy re-issue keeps group count exact
        issue_stage(ip, (c + 3) & 3);
        CP_COMMIT();
        int st = c & 3;
        panel_mma16<false>(acc, smb + st * 16384, smb + st * 16384 + 8192, warp_m, warp_n, lane);
    }

    const int g = lane >> 2, t = lane & 3;
#pragma unroll
    for (int mi = 0; mi < 4; mi++) {
        int m1 = m0 + warp_m + mi * 16 + g;
        int m2 = m1 + 8;
        float bv1 = bias[m1], bv2 = bias[m2];
#pragma unroll
        for (int ni = 0; ni < 4; ni++) {
            int nn = n0 + warp_n + ni * 8 + 2 * t;
            if (ADDZ) {
                float* ob = outp + (size_t)b * CC * HWS;
                *(float2*)(ob + (size_t)m1 * HWS + nn) =
                    make_float2(acc[mi][ni][0] + bv1, acc[mi][ni][1] + bv1);
                *(float2*)(ob + (size_t)m2 * HWS + nn) =
                    make_float2(acc[mi][ni][2] + bv2, acc[mi][ni][3] + bv2);
            } else {
                __nv_bfloat162* ob = (__nv_bfloat162*)g_botB + ((size_t)b * CC * HWS >> 1);
                ob[((size_t)m1 * HWS + nn) >> 1] =
                    __floats2bfloat162_rn(acc[mi][ni][0] + bv1, acc[mi][ni][1] + bv1);
                ob[((size_t)m2 * HWS + nn) >> 1] =
                    __floats2bfloat162_rn(acc[mi][ni][2] + bv2, acc[mi][ni][3] + bv2);
            }
        }
    }
}

// ---------------- S = cen @ top^T (fp16 hi/lo x3), 32KB smem (occ 2) ---------
__global__ void __launch_bounds__(256, 2) k_S_h()
{
    __shared__ uint32_t pan[8192];   // Ah | Al | Bh | Bl, 2048 u32 (8KB) each
    __shared__ float red[256];

    const int b   = blockIdx.z;
    const int n0  = blockIdx.x * 128;
    const int m0  = blockIdx.y * 128;
    const int tid = threadIdx.x;
    const int wid = tid >> 5, lane = tid & 31;
    const int warp_m = (wid & 1) * 64;
    const int warp_n = (wid >> 1) * 32;
    const int g = lane >> 2, t = lane & 3;
    const int r  = tid >> 1;
    const int hf = tid & 1;

    float acc[4][4][4];
#pragma unroll
    for (int mi = 0; mi < 4; mi++)
#pragma unroll
        for (int ni = 0; ni < 4; ni++)
#pragma unroll
            for (int e = 0; e < 4; e++) acc[mi][ni][e] = 0.f;

    const uint32_t pb  = s2u(pan);
    const uint32_t ahb = pb, alb = pb + 8192, bhb = pb + 16384, blb = pb + 24576;

    const int a_row = warp_m + (lane & 15);
    const int a_chk = (lane >> 4) << 2;
    const int b_row = warp_n + ((lane >> 4) << 3) + (lane & 7);
    const int b_chk = ((lane >> 3) & 1) << 2;

    for (int chk = 0; chk < 2; chk++) {
        __syncthreads();
        {
            size_t rowA = ((size_t)b * HWS + m0 + r) * 32 + chk * 16;   // u32 units
            size_t rowB = ((size_t)b * HWS + n0 + r) * 32 + chk * 16;
            const uint4* pAh = (const uint4*)((const uint32_t*)g_cenHh + rowA);
            const uint4* pAl = (const uint4*)((const uint32_t*)g_cenLh + rowA);
            const uint4* pBh = (const uint4*)((const uint32_t*)g_topHh + rowB);
            const uint4* pBl = (const uint4*)((const uint32_t*)g_topLh + rowB);
#pragma unroll
            for (int j = 0; j < 2; j++) {
                int cq = hf * 2 + j;
                int d  = r * 16 + ((cq ^ ((r >> 1) & 3)) << 2);
                *(uint4*)&pan[d]        = pAh[cq];
                *(uint4*)&pan[2048 + d] = pAl[cq];
                *(uint4*)&pan[4096 + d] = pBh[cq];
                *(uint4*)&pan[6144 + d] = pBl[cq];
            }
        }
        __syncthreads();
#pragma unroll
        for (int ks = 0; ks < 2; ks++) {
            int kb = ks * 8;
            uint32_t ah[4][4], al[4][4], bh[4][2], bl[4][2];
#pragma unroll
            for (int mi = 0; mi < 4; mi++) {
                uint32_t off = 4u * (uint32_t)sw16(a_row + mi * 16, kb + a_chk);
                LDSM4(ah[mi][0], ah[mi][1], ah[mi][2], ah[mi][3], ahb + off);
                LDSM4(al[mi][0], al[mi][1], al[mi][2], al[mi][3], alb + off);
            }
#pragma unroll
            for (int np = 0; np < 2; np++) {
                uint32_t off = 4u * (uint32_t)sw16(b_row + np * 16, kb + b_chk);
                LDSM4(bh[np*2][0], bh[np*2][1], bh[np*2+1][0], bh[np*2+1][1], bhb + off);
                LDSM4(bl[np*2][0], bl[np*2][1], bl[np*2+1][0], bl[np*2+1][1], blb + off);
            }
#pragma unroll
            for (int mi = 0; mi < 4; mi++)
#pragma unroll
                for (int ni = 0; ni < 4; ni++) {
                    mma16(acc[mi][ni], ah[mi], bh[ni]);
                    mma16(acc[mi][ni], ah[mi], bl[ni]);
                    mma16(acc[mi][ni], al[mi], bh[ni]);
                }
        }
    }

    // epilogue: E = bf16(exp(S - 40)); deterministic sum of the ROUNDED values
    __nv_bfloat162* Eb = (__nv_bfloat162*)(g_Eb + (size_t)b * HWS * HWS);
    float ls = 0.f;
#pragma unroll
    for (int mi = 0; mi < 4; mi++) {
        int m1 = m0 + warp_m + mi * 16 + g;
        int m2 = m1 + 8;
#pragma unroll
        for (int ni = 0; ni < 4; ni++) {
            int nn = n0 + warp_n + ni * 8 + 2 * t;
            __nv_bfloat16 h0 = __float2bfloat16(__expf(acc[mi][ni][0] - 40.f));
            __nv_bfloat16 h1 = __float2bfloat16(__expf(acc[mi][ni][1] - 40.f));
            __nv_bfloat16 h2 = __float2bfloat16(__expf(acc[mi][ni][2] - 40.f));
            __nv_bfloat16 h3 = __float2bfloat16(__expf(acc[mi][ni][3] - 40.f));
            ls += (__bfloat162float(h0) + __bfloat162float(h1)) +
                  (__bfloat162float(h2) + __bfloat162float(h3));
            Eb[((size_t)m1 * HWS + nn) >> 1] = __nv_bfloat162(h0, h1);
            Eb[((size_t)m2 * HWS + nn) >> 1] = __nv_bfloat162(h2, h3);
        }
    }
    red[tid] = ls;
    __syncthreads();
    for (int st = 128; st > 0; st >>= 1) {
        if (tid < st) red[tid] += red[tid + st];
        __syncthreads();
    }
    if (tid == 0) g_partialS[b * 1024 + blockIdx.y * 32 + blockIdx.x] = red[0];
}

// ---------------- reduce partial sums ----------------------------------------
__global__ void k_sumreduce()
{
    const int b = blockIdx.x;
    const int tid = threadIdx.x;
    __shared__ float red[256];
    float s = 0.f;
    for (int i = tid; i < 1024; i += 256) s += g_partialS[b * 1024 + i];
    red[tid] = s;
    __syncthreads();
    for (int st = 128; st > 0; st >>= 1) {
        if (tid < st) red[tid] += red[tid + st];
        __syncthreads();
    }
    if (tid == 0) g_sum[b] = red[0];
}

// ---------------- attn: (E/sum)@bottomT^T bf16, 4-stage; writes x+attn -------
__global__ void __launch_bounds__(256, 2) k_attn_h(const float* __restrict__ x)
{
    extern __shared__ uint32_t sm[];   // 4 stages x (A 2048 + B 2048 u32) = 64KB
    const uint32_t smb = s2u(sm);

    const int b   = blockIdx.z;
    const int cb  = blockIdx.x * 128;   // C tile
    const int m0  = blockIdx.y * 128;   // HW tile
    const int tid = threadIdx.x;
    const int wid = tid >> 5, lane = tid & 31;
    const int warp_m = (wid & 1) * 64;
    const int warp_n = (wid >> 1) * 32;

    const int r  = tid >> 1;
    const int hf = tid & 1;

    const uint32_t* Arow = (const uint32_t*)g_Eb + ((size_t)b * HWS + m0 + r) * HWS2;
    const uint32_t* Brow = (const uint32_t*)g_botB + ((size_t)b * CC + cb + r) * HWS2;

    float acc[4][4][4];
#pragma unroll
    for (int mi = 0; mi < 4; mi++)
#pragma unroll
        for (int ni = 0; ni < 4; ni++)
#pragma unroll
            for (int e = 0; e < 4; e++) acc[mi][ni][e] = 0.f;

    auto issue_stage = [&](int c, int st) {
        uint32_t ab = smb + st * 16384;
        uint32_t bb = ab + 8192;
        int ku = c * 16;   // u32 offset of this k32 panel
#pragma unroll
        for (int j = 0; j < 2; j++) {
            int cq = hf * 2 + j;
            uint32_t off = 4u * (uint32_t)(r * 16 + ((cq ^ ((r >> 1) & 3)) << 2));
            cpa16(ab + off, Arow + ku + cq * 4);
            cpa16(bb + off, Brow + ku + cq * 4);
        }
    };

    const int NC = 128;
    issue_stage(0, 0); CP_COMMIT();
    issue_stage(1, 1); CP_COMMIT();
    issue_stage(2, 2); CP_COMMIT();

    for (int c = 0; c < NC; c++) {
        CP_WAIT(2);
        __syncthreads();
        int ip = (c + 3 < NC) ? c + 3 : 0;
        issue_stage(ip, (c + 3) & 3);
        CP_COMMIT();
        int st = c & 3;
        panel_mma16<true>(acc, smb + st * 16384, smb + st * 16384 + 8192, warp_m, warp_n, lane);
    }

    const int g = lane >> 2, t = lane & 3;
    const float inv = 1.0f / g_sum[b];
    const float* xb = x + (size_t)b * CC * HWS;
    __half* zb = g_xzh + (size_t)b * CC * HWS;

#pragma unroll
    for (int mi = 0; mi < 4; mi++) {
        int mrows[2] = { m0 + warp_m + mi * 16 + g, m0 + warp_m + mi * 16 + g + 8 };
#pragma unroll
        for (int ni = 0; ni < 4; ni++) {
            int nn = cb + warp_n + ni * 8 + 2 * t;
#pragma unroll
            for (int hrow = 0; hrow < 2; hrow++) {
                int f = mrows[hrow] * CC + nn;
                float2 xv = *(const float2*)(xb + f);
                float v0 = xv.x + acc[mi][ni][hrow * 2 + 0] * inv;
                float v1 = xv.y + acc[mi][ni][hrow * 2 + 1] * inv;
                // 8-interleave scatter: element (c,hw) -> ((c>>3)*HWS + hw)*8 + (c&7)
                int c0 = f >> 12,        hw0 = f & 4095;
                int c1 = (f + 1) >> 12,  hw1 = (f + 1) & 4095;
                zb[(((size_t)(c0 >> 3) * HWS + hw0) << 3) + (c0 & 7)] = __float2half_rn(v0);
                zb[(((size_t)(c1 >> 3) * HWS + hw1) << 3) + (c1 & 7)] = __float2half_rn(v1);
            }
        }
    }
}

// ---------------- launch -----------------------------------------------------
extern "C" void kernel_launch(void* const* d_in, const int* in_sizes, int n_in,
                              void* d_out, int out_size)
{
    const float* x   = (const float*)d_in[0];
    const float* wt  = (const float*)d_in[1];
    const float* bt  = (const float*)d_in[2];
    const float* wc  = (const float*)d_in[3];
    const float* bc  = (const float*)d_in[4];
    const float* wb  = (const float*)d_in[5];
    const float* bbm = (const float*)d_in[6];
    const float* wo  = (const float*)d_in[7];
    const float* bo  = (const float*)d_in[8];
    float* out = (float*)d_out;

    cudaFuncSetAttribute(k_conv_h<false>, cudaFuncAttributeMaxDynamicSharedMemorySize, 65536);
    cudaFuncSetAttribute(k_conv_h<true>,  cudaFuncAttributeMaxDynamicSharedMemorySize, 65536);
    cudaFuncSetAttribute(k_attn_h,        cudaFuncAttributeMaxDynamicSharedMemorySize, 65536);

    k_wtransH2<<<(2 * CC * 2304 + 255) / 256, 256>>>(wb, wo);
    k_top_center<<<dim3(HWS / 64, BB), 256>>>(x, wt, bt, wc, bc);
    k_conv_h<false><<<dim3(32, 2, BB), 256, 65536>>>(bbm, nullptr);
    k_S_h<<<dim3(32, 32, BB), 256>>>();
    k_sumreduce<<<BB, 256>>>();
    k_attn_h<<<dim3(2, 32, BB), 256, 65536>>>(x);
    k_conv_h<true><<<dim3(32, 2, BB), 256, 65536>>>(bo, out);
}